// round 4
// baseline (speedup 1.0000x reference)
#include <cuda_runtime.h>
#include <math.h>

#define TT 64
#define DM 16
#define DFF 32
#define EPSF 1e-5f

typedef unsigned long long u64;

// ---- constant-memory parameters (device-to-device copied at launch) ----
__constant__ float cWk[DM][DM];
__constant__ float cWq[DM][DM];
__constant__ float cWv[DM][DM];
__constant__ float cW1[DM][DFF];
__constant__ float cW2[DFF][DM];
__constant__ float cb1v[DFF];
__constant__ float cb2v[DM];
__constant__ float cg1v[DM];
__constant__ float cB1v[DM];
__constant__ float cg2v[DM];
__constant__ float cB2v[DM];

__device__ __forceinline__ u64 pk2(float lo, float hi) {
    u64 r; asm("mov.b64 %0,{%1,%2};" : "=l"(r) : "f"(lo), "f"(hi)); return r;
}
__device__ __forceinline__ float2 up2(u64 v) {
    float2 f; asm("mov.b64 {%0,%1},%2;" : "=f"(f.x), "=f"(f.y) : "l"(v)); return f;
}
__device__ __forceinline__ u64 f2fma(u64 a, u64 b, u64 c) {
    u64 d; asm("fma.rn.f32x2 %0,%1,%2,%3;" : "=l"(d) : "l"(a), "l"(b), "l"(c)); return d;
}
__device__ __forceinline__ u64 f2add(u64 a, u64 b) {
    u64 d; asm("add.rn.f32x2 %0,%1,%2;" : "=l"(d) : "l"(a), "l"(b)); return d;
}
__device__ __forceinline__ u64 f2mul(u64 a, u64 b) {
    u64 d; asm("mul.rn.f32x2 %0,%1,%2;" : "=l"(d) : "l"(a), "l"(b)); return d;
}
// smem: one LDS.128 -> two packed pairs
__device__ __forceinline__ void ld2(const float* p, u64& a, u64& b) {
    float4 v = *reinterpret_cast<const float4*>(p);
    a = pk2(v.x, v.y); b = pk2(v.z, v.w);
}

// LayerNorm over 16 channels (8 packed pairs) with constant g/b arrays
template <int WHICH>
__device__ __forceinline__ void ln16c(const u64* xp, float* hs)
{
    u64 acc = f2add(f2add(f2add(xp[0], xp[1]), f2add(xp[2], xp[3])),
                    f2add(f2add(xp[4], xp[5]), f2add(xp[6], xp[7])));
    float2 s2 = up2(acc);
    float mu = (s2.x + s2.y) * (1.0f / DM);
    u64 nmu = pk2(-mu, -mu);
    u64 v0 = 0ull, v1 = 0ull;
    #pragma unroll
    for (int i = 0; i < 8; i += 2) {
        u64 d0 = f2add(xp[i], nmu);     v0 = f2fma(d0, d0, v0);
        u64 d1 = f2add(xp[i + 1], nmu); v1 = f2fma(d1, d1, v1);
    }
    s2 = up2(f2add(v0, v1));
    float rstd = rsqrtf((s2.x + s2.y) * (1.0f / DM) + EPSF);
    #pragma unroll
    for (int c = 0; c < DM; c++) {
        float g = (WHICH == 1) ? cg1v[c] : cg2v[c];
        float bb = (WHICH == 1) ? cB1v[c] : cB2v[c];
        float2 xv = up2(xp[c >> 1]);
        float xc = (c & 1) ? xv.y : xv.x;
        hs[c] = (xc - mu) * rstd * g + bb;
    }
}

// 16x16 projection for two tokens from constant weights
__device__ __forceinline__ void proj2c(const float (&W)[DM][DM],
                                       const float* hA, const float* hB,
                                       u64* aA, u64* aB)
{
    #pragma unroll
    for (int i = 0; i < 8; i++) { aA[i] = 0ull; aB[i] = 0ull; }
    #pragma unroll
    for (int c = 0; c < DM; c++) {
        u64 hbA = pk2(hA[c], hA[c]);
        u64 hbB = pk2(hB[c], hB[c]);
        #pragma unroll
        for (int i = 0; i < 8; i++) {
            u64 wp = pk2(W[c][2 * i], W[c][2 * i + 1]);
            aA[i] = f2fma(hbA, wp, aA[i]);
            aB[i] = f2fma(hbB, wp, aB[i]);
        }
    }
}

__device__ __forceinline__ void st_row(float* p, const u64* a)
{
    #pragma unroll
    for (int i = 0; i < 4; i++) {
        float2 lo = up2(a[2 * i]), hi = up2(a[2 * i + 1]);
        *reinterpret_cast<float4*>(p + 4 * i) = make_float4(lo.x, lo.y, hi.x, hi.y);
    }
}

__global__ __launch_bounds__(128, 3)
void block_kernel(const float* __restrict__ x, float* __restrict__ out)
{
    __shared__ float sK[4][TT][DM], sV[4][TT][DM];

    const int tid = threadIdx.x;
    const int w   = tid >> 5;          // warp = one batch element
    const int t   = tid & 31;          // token A = t, token B = t + 32
    const long long b = (long long)blockIdx.x * 4 + w;

    // ---- load both token rows ----
    u64 xA[8], xB[8];
    const float* xa = x + (b * TT + t) * DM;
    #pragma unroll
    for (int i = 0; i < 4; i++) {
        float4 v4 = *reinterpret_cast<const float4*>(xa + 4 * i);
        xA[2 * i] = pk2(v4.x, v4.y); xA[2 * i + 1] = pk2(v4.z, v4.w);
        float4 w4 = *reinterpret_cast<const float4*>(xa + 32 * DM + 4 * i);
        xB[2 * i] = pk2(w4.x, w4.y); xB[2 * i + 1] = pk2(w4.z, w4.w);
    }

    // ---- LN1 ----
    float hA[DM], hB[DM];
    ln16c<1>(xA, hA);
    ln16c<1>(xB, hB);

    // ---- K, V, Q projections (phased) ----
    {
        u64 aA[8], aB[8];
        proj2c(cWk, hA, hB, aA, aB);
        st_row(&sK[w][t][0], aA);
        st_row(&sK[w][t + 32][0], aB);
        proj2c(cWv, hA, hB, aA, aB);
        st_row(&sV[w][t][0], aA);
        st_row(&sV[w][t + 32][0], aB);
    }
    u64 qA[8], qB[8];
    proj2c(cWq, hA, hB, qA, qB);
    {
        u64 qt = pk2(0.25f, 0.25f);     // fold 1/sqrt(C)
        #pragma unroll
        for (int i = 0; i < 8; i++) { qA[i] = f2mul(qA[i], qt); qB[i] = f2mul(qB[i], qt); }
    }
    __syncwarp();      // K/V tile is warp-private

    // ---- causal attention: single pass, no max subtraction ----
    float lA = 0.f, lB = 0.f;
    u64 yA[8], yB[8];
    #pragma unroll
    for (int i = 0; i < 8; i++) { yA[i] = 0ull; yB[i] = 0ull; }

    const float (*Kw)[DM] = sK[w];
    const float (*Vw)[DM] = sV[w];

    #pragma unroll
    for (int s = 0; s < 32; s++) {
        u64 kr[8];
        ld2(&Kw[s][0], kr[0], kr[1]); ld2(&Kw[s][4], kr[2], kr[3]);
        ld2(&Kw[s][8], kr[4], kr[5]); ld2(&Kw[s][12], kr[6], kr[7]);
        u64 a0 = 0ull, a1 = 0ull, b0 = 0ull, b1_ = 0ull;
        #pragma unroll
        for (int i = 0; i < 4; i++) {
            a0  = f2fma(qA[2 * i],     kr[2 * i],     a0);
            a1  = f2fma(qA[2 * i + 1], kr[2 * i + 1], a1);
            b0  = f2fma(qB[2 * i],     kr[2 * i],     b0);
            b1_ = f2fma(qB[2 * i + 1], kr[2 * i + 1], b1_);
        }
        float2 fa = up2(f2add(a0, a1)), fb = up2(f2add(b0, b1_));
        float pA = (s <= t) ? __expf(fa.x + fa.y) : 0.f;
        float pB = __expf(fb.x + fb.y);
        lA += pA; lB += pB;
        u64 vr[8];
        ld2(&Vw[s][0], vr[0], vr[1]); ld2(&Vw[s][4], vr[2], vr[3]);
        ld2(&Vw[s][8], vr[4], vr[5]); ld2(&Vw[s][12], vr[6], vr[7]);
        u64 pAp = pk2(pA, pA), pBp = pk2(pB, pB);
        #pragma unroll
        for (int i = 0; i < 8; i++) {
            yA[i] = f2fma(pAp, vr[i], yA[i]);
            yB[i] = f2fma(pBp, vr[i], yB[i]);
        }
    }
    #pragma unroll
    for (int s = 32; s < TT; s++) {
        u64 kr[8];
        ld2(&Kw[s][0], kr[0], kr[1]); ld2(&Kw[s][4], kr[2], kr[3]);
        ld2(&Kw[s][8], kr[4], kr[5]); ld2(&Kw[s][12], kr[6], kr[7]);
        u64 b0 = 0ull, b1_ = 0ull;
        #pragma unroll
        for (int i = 0; i < 4; i++) {
            b0  = f2fma(qB[2 * i],     kr[2 * i],     b0);
            b1_ = f2fma(qB[2 * i + 1], kr[2 * i + 1], b1_);
        }
        float2 fb = up2(f2add(b0, b1_));
        float pB = (t >= s - 32) ? __expf(fb.x + fb.y) : 0.f;
        lB += pB;
        u64 vr[8];
        ld2(&Vw[s][0], vr[0], vr[1]); ld2(&Vw[s][4], vr[2], vr[3]);
        ld2(&Vw[s][8], vr[4], vr[5]); ld2(&Vw[s][12], vr[6], vr[7]);
        u64 pBp = pk2(pB, pB);
        #pragma unroll
        for (int i = 0; i < 8; i++) yB[i] = f2fma(pBp, vr[i], yB[i]);
    }

    {   // residual 1
        float invA = __fdividef(1.0f, lA), invB = __fdividef(1.0f, lB);
        u64 ia = pk2(invA, invA), ib = pk2(invB, invB);
        #pragma unroll
        for (int i = 0; i < 8; i++) {
            xA[i] = f2fma(yA[i], ia, xA[i]);
            xB[i] = f2fma(yB[i], ib, xB[i]);
        }
    }

    // ---- LN2 ----
    ln16c<2>(xA, hA);
    ln16c<2>(xB, hB);

    // ---- FFN1: f = h2 @ W1 + b1 ----
    u64 fA[16], fB[16];
    #pragma unroll
    for (int i = 0; i < 16; i++) {
        u64 bp = pk2(cb1v[2 * i], cb1v[2 * i + 1]);
        fA[i] = bp; fB[i] = bp;
    }
    #pragma unroll
    for (int c = 0; c < DM; c++) {
        u64 hbA = pk2(hA[c], hA[c]);
        u64 hbB = pk2(hB[c], hB[c]);
        #pragma unroll
        for (int i = 0; i < 16; i++) {
            u64 wp = pk2(cW1[c][2 * i], cW1[c][2 * i + 1]);
            fA[i] = f2fma(hbA, wp, fA[i]);
            fB[i] = f2fma(hbB, wp, fB[i]);
        }
    }
    // exact GELU
    float fsA[DFF], fsB[DFF];
    #pragma unroll
    for (int i = 0; i < 16; i++) {
        float2 fa = up2(fA[i]), fb = up2(fB[i]);
        fsA[2 * i]     = 0.5f * fa.x * (1.0f + erff(fa.x * 0.70710678118654752f));
        fsA[2 * i + 1] = 0.5f * fa.y * (1.0f + erff(fa.y * 0.70710678118654752f));
        fsB[2 * i]     = 0.5f * fb.x * (1.0f + erff(fb.x * 0.70710678118654752f));
        fsB[2 * i + 1] = 0.5f * fb.y * (1.0f + erff(fb.y * 0.70710678118654752f));
    }

    // ---- FFN2 + residual ----
    u64 oA[8], oB[8];
    #pragma unroll
    for (int i = 0; i < 8; i++) {
        u64 bp = pk2(cb2v[2 * i], cb2v[2 * i + 1]);
        oA[i] = f2add(xA[i], bp);
        oB[i] = f2add(xB[i], bp);
    }
    #pragma unroll
    for (int j = 0; j < DFF; j++) {
        u64 fbA = pk2(fsA[j], fsA[j]);
        u64 fbB = pk2(fsB[j], fsB[j]);
        #pragma unroll
        for (int i = 0; i < 8; i++) {
            u64 wp = pk2(cW2[j][2 * i], cW2[j][2 * i + 1]);
            oA[i] = f2fma(fbA, wp, oA[i]);
            oB[i] = f2fma(fbB, wp, oB[i]);
        }
    }

    // ---- store both tokens ----
    float* op = out + (b * TT + t) * DM;
    st_row(op, oA);
    st_row(op + 32 * DM, oB);
}

extern "C" void kernel_launch(void* const* d_in, const int* in_sizes, int n_in,
                              void* d_out, int out_size)
{
    const float* x = (const float*)d_in[0];
    float* out = (float*)d_out;

    // device-to-device copies into constant memory (graph-capturable)
    cudaMemcpyToSymbolAsync(cWk,  d_in[1], DM * DM * sizeof(float), 0, cudaMemcpyDeviceToDevice);
    cudaMemcpyToSymbolAsync(cWq,  d_in[2], DM * DM * sizeof(float), 0, cudaMemcpyDeviceToDevice);
    cudaMemcpyToSymbolAsync(cWv,  d_in[3], DM * DM * sizeof(float), 0, cudaMemcpyDeviceToDevice);
    cudaMemcpyToSymbolAsync(cg1v, d_in[4], DM * sizeof(float), 0, cudaMemcpyDeviceToDevice);
    cudaMemcpyToSymbolAsync(cB1v, d_in[5], DM * sizeof(float), 0, cudaMemcpyDeviceToDevice);
    cudaMemcpyToSymbolAsync(cg2v, d_in[6], DM * sizeof(float), 0, cudaMemcpyDeviceToDevice);
    cudaMemcpyToSymbolAsync(cB2v, d_in[7], DM * sizeof(float), 0, cudaMemcpyDeviceToDevice);
    cudaMemcpyToSymbolAsync(cW1,  d_in[8], DM * DFF * sizeof(float), 0, cudaMemcpyDeviceToDevice);
    cudaMemcpyToSymbolAsync(cb1v, d_in[9], DFF * sizeof(float), 0, cudaMemcpyDeviceToDevice);
    cudaMemcpyToSymbolAsync(cW2,  d_in[10], DFF * DM * sizeof(float), 0, cudaMemcpyDeviceToDevice);
    cudaMemcpyToSymbolAsync(cb2v, d_in[11], DM * sizeof(float), 0, cudaMemcpyDeviceToDevice);

    int B = in_sizes[0] / (TT * DM);
    dim3 grid((B + 3) / 4);               // 4 batch elements per CTA (1 per warp)
    block_kernel<<<grid, 128>>>(x, out);
}

// round 5
// speedup vs baseline: 1.0877x; 1.0877x over previous
#include <cuda_runtime.h>
#include <math.h>

#define TT 64
#define DM 16
#define DFF 32
#define EPSF 1e-5f

// flat parameter bank offsets (floats)
#define OFF_WK  0
#define OFF_WQ  256
#define OFF_WV  512
#define OFF_W1  768
#define OFF_W2  1280
#define OFF_B1  1792
#define OFF_B2  1824
#define OFF_G1  1840
#define OFF_BE1 1856
#define OFF_G2  1872
#define OFF_BE2 1888
#define NPARAM  1904

__constant__ float cPf[NPARAM];
__device__   float gPf[NPARAM];

typedef unsigned long long u64;

__device__ __forceinline__ u64 pk2(float lo, float hi) {
    u64 r; asm("mov.b64 %0,{%1,%2};" : "=l"(r) : "f"(lo), "f"(hi)); return r;
}
__device__ __forceinline__ float2 up2(u64 v) {
    float2 f; asm("mov.b64 {%0,%1},%2;" : "=f"(f.x), "=f"(f.y) : "l"(v)); return f;
}
__device__ __forceinline__ u64 f2fma(u64 a, u64 b, u64 c) {
    u64 d; asm("fma.rn.f32x2 %0,%1,%2,%3;" : "=l"(d) : "l"(a), "l"(b), "l"(c)); return d;
}
__device__ __forceinline__ u64 f2add(u64 a, u64 b) {
    u64 d; asm("add.rn.f32x2 %0,%1,%2;" : "=l"(d) : "l"(a), "l"(b)); return d;
}
__device__ __forceinline__ u64 f2mul(u64 a, u64 b) {
    u64 d; asm("mul.rn.f32x2 %0,%1,%2;" : "=l"(d) : "l"(a), "l"(b)); return d;
}
__device__ __forceinline__ void ld2(const float* p, u64& a, u64& b) {
    float4 v = *reinterpret_cast<const float4*>(p);
    a = pk2(v.x, v.y); b = pk2(v.z, v.w);
}

// ---- pack kernel: gather 11 param arrays into one __device__ buffer ----
__global__ void pack_kernel(const float* Wk, const float* Wq, const float* Wv,
                            const float* g1, const float* B1,
                            const float* g2, const float* B2,
                            const float* W1, const float* b1,
                            const float* W2, const float* b2)
{
    int i = threadIdx.x;
    if (i < 256) { gPf[OFF_WK + i] = Wk[i]; gPf[OFF_WQ + i] = Wq[i]; gPf[OFF_WV + i] = Wv[i]; }
    for (int j = i; j < 512; j += 256) { gPf[OFF_W1 + j] = W1[j]; gPf[OFF_W2 + j] = W2[j]; }
    if (i < DFF) gPf[OFF_B1 + i] = b1[i];
    if (i < DM) {
        gPf[OFF_B2 + i]  = b2[i];
        gPf[OFF_G1 + i]  = g1[i];
        gPf[OFF_BE1 + i] = B1[i];
        gPf[OFF_G2 + i]  = g2[i];
        gPf[OFF_BE2 + i] = B2[i];
    }
}

// LayerNorm over 16 channels (8 packed pairs), params from constant bank
template <int GOFF, int BOFF>
__device__ __forceinline__ void ln16c(const u64* xp, float* hs)
{
    u64 acc = f2add(f2add(f2add(xp[0], xp[1]), f2add(xp[2], xp[3])),
                    f2add(f2add(xp[4], xp[5]), f2add(xp[6], xp[7])));
    float2 s2 = up2(acc);
    float mu = (s2.x + s2.y) * (1.0f / DM);
    u64 nmu = pk2(-mu, -mu);
    u64 v0 = 0ull, v1 = 0ull;
    #pragma unroll
    for (int i = 0; i < 8; i += 2) {
        u64 d0 = f2add(xp[i], nmu);     v0 = f2fma(d0, d0, v0);
        u64 d1 = f2add(xp[i + 1], nmu); v1 = f2fma(d1, d1, v1);
    }
    s2 = up2(f2add(v0, v1));
    float rstd = rsqrtf((s2.x + s2.y) * (1.0f / DM) + EPSF);
    #pragma unroll
    for (int c = 0; c < DM; c++) {
        float2 xv = up2(xp[c >> 1]);
        float xc = (c & 1) ? xv.y : xv.x;
        hs[c] = (xc - mu) * rstd * cPf[GOFF + c] + cPf[BOFF + c];
    }
}

// 16x16 projection for two tokens from constant weights (flat, compile-time base)
template <int WOFF>
__device__ __forceinline__ void proj2c(const float* hA, const float* hB, u64* aA, u64* aB)
{
    #pragma unroll
    for (int i = 0; i < 8; i++) { aA[i] = 0ull; aB[i] = 0ull; }
    #pragma unroll
    for (int c = 0; c < DM; c++) {
        u64 hbA = pk2(hA[c], hA[c]);
        u64 hbB = pk2(hB[c], hB[c]);
        #pragma unroll
        for (int i = 0; i < 8; i++) {
            u64 wp = pk2(cPf[WOFF + c * DM + 2 * i], cPf[WOFF + c * DM + 2 * i + 1]);
            aA[i] = f2fma(hbA, wp, aA[i]);
            aB[i] = f2fma(hbB, wp, aB[i]);
        }
    }
}

__device__ __forceinline__ void st_row(float* p, const u64* a)
{
    #pragma unroll
    for (int i = 0; i < 4; i++) {
        float2 lo = up2(a[2 * i]), hi = up2(a[2 * i + 1]);
        *reinterpret_cast<float4*>(p + 4 * i) = make_float4(lo.x, lo.y, hi.x, hi.y);
    }
}

// FFN for ONE token: xp[8] holds residual input, overwritten with final output
__device__ __forceinline__ void ffn_token(const float* hs, u64* xp)
{
    u64 f[16];
    #pragma unroll
    for (int i = 0; i < 16; i++)
        f[i] = pk2(cPf[OFF_B1 + 2 * i], cPf[OFF_B1 + 2 * i + 1]);
    #pragma unroll
    for (int c = 0; c < DM; c++) {
        u64 hb = pk2(hs[c], hs[c]);
        #pragma unroll
        for (int i = 0; i < 16; i++) {
            u64 wp = pk2(cPf[OFF_W1 + c * DFF + 2 * i], cPf[OFF_W1 + c * DFF + 2 * i + 1]);
            f[i] = f2fma(hb, wp, f[i]);
        }
    }
    float fs[DFF];
    #pragma unroll
    for (int i = 0; i < 16; i++) {
        float2 fa = up2(f[i]);
        fs[2 * i]     = 0.5f * fa.x * (1.0f + erff(fa.x * 0.70710678118654752f));
        fs[2 * i + 1] = 0.5f * fa.y * (1.0f + erff(fa.y * 0.70710678118654752f));
    }
    u64 o[8];
    #pragma unroll
    for (int i = 0; i < 8; i++)
        o[i] = f2add(xp[i], pk2(cPf[OFF_B2 + 2 * i], cPf[OFF_B2 + 2 * i + 1]));
    #pragma unroll
    for (int j = 0; j < DFF; j++) {
        u64 fb = pk2(fs[j], fs[j]);
        #pragma unroll
        for (int i = 0; i < 8; i++) {
            u64 wp = pk2(cPf[OFF_W2 + j * DM + 2 * i], cPf[OFF_W2 + j * DM + 2 * i + 1]);
            o[i] = f2fma(fb, wp, o[i]);
        }
    }
    #pragma unroll
    for (int i = 0; i < 8; i++) xp[i] = o[i];
}

__global__ __launch_bounds__(128, 4)
void block_kernel(const float* __restrict__ x, float* __restrict__ out)
{
    __shared__ float sK[4][TT][DM], sV[4][TT][DM];

    const int tid = threadIdx.x;
    const int w   = tid >> 5;          // warp = one batch element
    const int t   = tid & 31;          // token A = t, token B = t + 32
    const long long b = (long long)blockIdx.x * 4 + w;

    // ---- load both token rows ----
    u64 xA[8], xB[8];
    const float* xa = x + (b * TT + t) * DM;
    #pragma unroll
    for (int i = 0; i < 4; i++) {
        float4 v4 = *reinterpret_cast<const float4*>(xa + 4 * i);
        xA[2 * i] = pk2(v4.x, v4.y); xA[2 * i + 1] = pk2(v4.z, v4.w);
        float4 w4 = *reinterpret_cast<const float4*>(xa + 32 * DM + 4 * i);
        xB[2 * i] = pk2(w4.x, w4.y); xB[2 * i + 1] = pk2(w4.z, w4.w);
    }

    // ---- LN1 ----
    float hA[DM], hB[DM];
    ln16c<OFF_G1, OFF_BE1>(xA, hA);
    ln16c<OFF_G1, OFF_BE1>(xB, hB);

    // ---- K, V, Q projections (phased) ----
    {
        u64 aA[8], aB[8];
        proj2c<OFF_WK>(hA, hB, aA, aB);
        st_row(&sK[w][t][0], aA);
        st_row(&sK[w][t + 32][0], aB);
        proj2c<OFF_WV>(hA, hB, aA, aB);
        st_row(&sV[w][t][0], aA);
        st_row(&sV[w][t + 32][0], aB);
    }
    u64 qA[8], qB[8];
    proj2c<OFF_WQ>(hA, hB, qA, qB);
    {
        u64 qt = pk2(0.25f, 0.25f);     // fold 1/sqrt(C)
        #pragma unroll
        for (int i = 0; i < 8; i++) { qA[i] = f2mul(qA[i], qt); qB[i] = f2mul(qB[i], qt); }
    }
    __syncwarp();      // K/V tile is warp-private

    // ---- causal attention: single pass, no max subtraction ----
    float lA = 0.f, lB = 0.f;
    u64 yA[8], yB[8];
    #pragma unroll
    for (int i = 0; i < 8; i++) { yA[i] = 0ull; yB[i] = 0ull; }

    const float (*Kw)[DM] = sK[w];
    const float (*Vw)[DM] = sV[w];

    #pragma unroll
    for (int s = 0; s < 32; s++) {
        u64 kr[8];
        ld2(&Kw[s][0], kr[0], kr[1]); ld2(&Kw[s][4], kr[2], kr[3]);
        ld2(&Kw[s][8], kr[4], kr[5]); ld2(&Kw[s][12], kr[6], kr[7]);
        u64 a0 = 0ull, a1 = 0ull, b0 = 0ull, b1_ = 0ull;
        #pragma unroll
        for (int i = 0; i < 4; i++) {
            a0  = f2fma(qA[2 * i],     kr[2 * i],     a0);
            a1  = f2fma(qA[2 * i + 1], kr[2 * i + 1], a1);
            b0  = f2fma(qB[2 * i],     kr[2 * i],     b0);
            b1_ = f2fma(qB[2 * i + 1], kr[2 * i + 1], b1_);
        }
        float2 fa = up2(f2add(a0, a1)), fb = up2(f2add(b0, b1_));
        float pA = (s <= t) ? __expf(fa.x + fa.y) : 0.f;
        float pB = __expf(fb.x + fb.y);
        lA += pA; lB += pB;
        u64 vr[8];
        ld2(&Vw[s][0], vr[0], vr[1]); ld2(&Vw[s][4], vr[2], vr[3]);
        ld2(&Vw[s][8], vr[4], vr[5]); ld2(&Vw[s][12], vr[6], vr[7]);
        u64 pAp = pk2(pA, pA), pBp = pk2(pB, pB);
        #pragma unroll
        for (int i = 0; i < 8; i++) {
            yA[i] = f2fma(pAp, vr[i], yA[i]);
            yB[i] = f2fma(pBp, vr[i], yB[i]);
        }
    }
    #pragma unroll
    for (int s = 32; s < TT; s++) {
        u64 kr[8];
        ld2(&Kw[s][0], kr[0], kr[1]); ld2(&Kw[s][4], kr[2], kr[3]);
        ld2(&Kw[s][8], kr[4], kr[5]); ld2(&Kw[s][12], kr[6], kr[7]);
        u64 b0 = 0ull, b1_ = 0ull;
        #pragma unroll
        for (int i = 0; i < 4; i++) {
            b0  = f2fma(qB[2 * i],     kr[2 * i],     b0);
            b1_ = f2fma(qB[2 * i + 1], kr[2 * i + 1], b1_);
        }
        float2 fb = up2(f2add(b0, b1_));
        float pB = (t >= s - 32) ? __expf(fb.x + fb.y) : 0.f;
        lB += pB;
        u64 vr[8];
        ld2(&Vw[s][0], vr[0], vr[1]); ld2(&Vw[s][4], vr[2], vr[3]);
        ld2(&Vw[s][8], vr[4], vr[5]); ld2(&Vw[s][12], vr[6], vr[7]);
        u64 pBp = pk2(pB, pB);
        #pragma unroll
        for (int i = 0; i < 8; i++) yB[i] = f2fma(pBp, vr[i], yB[i]);
    }

    {   // residual 1
        float invA = __fdividef(1.0f, lA), invB = __fdividef(1.0f, lB);
        u64 ia = pk2(invA, invA), ib = pk2(invB, invB);
        #pragma unroll
        for (int i = 0; i < 8; i++) {
            xA[i] = f2fma(yA[i], ia, xA[i]);
            xB[i] = f2fma(yB[i], ib, xB[i]);
        }
    }

    // ---- LN2 + FFN, token-sequential (halves live registers) ----
    float* op = out + (b * TT + t) * DM;
    {
        float hs[DM];
        ln16c<OFF_G2, OFF_BE2>(xA, hs);
        ffn_token(hs, xA);
        st_row(op, xA);
    }
    {
        float hs[DM];
        ln16c<OFF_G2, OFF_BE2>(xB, hs);
        ffn_token(hs, xB);
        st_row(op + 32 * DM, xB);
    }
}

extern "C" void kernel_launch(void* const* d_in, const int* in_sizes, int n_in,
                              void* d_out, int out_size)
{
    const float* x = (const float*)d_in[0];
    float* out = (float*)d_out;

    // 1) gather all params into one device buffer (one kernel node)
    pack_kernel<<<1, 256>>>((const float*)d_in[1], (const float*)d_in[2],
                            (const float*)d_in[3], (const float*)d_in[4],
                            (const float*)d_in[5], (const float*)d_in[6],
                            (const float*)d_in[7], (const float*)d_in[8],
                            (const float*)d_in[9], (const float*)d_in[10],
                            (const float*)d_in[11]);
    // 2) single D2D copy into the constant bank (one memcpy node)
    void* src = nullptr;
    cudaGetSymbolAddress(&src, gPf);
    cudaMemcpyToSymbolAsync(cPf, src, NPARAM * sizeof(float), 0,
                            cudaMemcpyDeviceToDevice);

    int B = in_sizes[0] / (TT * DM);
    dim3 grid((B + 3) / 4);               // 4 batch elements per CTA (1 per warp)
    block_kernel<<<grid, 128>>>(x, out);
}

// round 6
// speedup vs baseline: 1.1319x; 1.0407x over previous
#include <cuda_runtime.h>
#include <math.h>

#define TT 64
#define DM 16
#define DFF 32
#define EPSF 1e-5f

// flat parameter bank offsets (floats)
#define OFF_WK  0
#define OFF_WQ  256
#define OFF_WV  512
#define OFF_W1  768
#define OFF_W2  1280
#define OFF_B1  1792
#define OFF_B2  1824
#define OFF_G1  1840
#define OFF_BE1 1856
#define OFF_G2  1872
#define OFF_BE2 1888
#define NPARAM  1904

__constant__ float cPf[NPARAM];
__device__   float gPf[NPARAM];

typedef unsigned long long u64;

__device__ __forceinline__ u64 pk2(float lo, float hi) {
    u64 r; asm("mov.b64 %0,{%1,%2};" : "=l"(r) : "f"(lo), "f"(hi)); return r;
}
__device__ __forceinline__ float2 up2(u64 v) {
    float2 f; asm("mov.b64 {%0,%1},%2;" : "=f"(f.x), "=f"(f.y) : "l"(v)); return f;
}
__device__ __forceinline__ u64 f2fma(u64 a, u64 b, u64 c) {
    u64 d; asm("fma.rn.f32x2 %0,%1,%2,%3;" : "=l"(d) : "l"(a), "l"(b), "l"(c)); return d;
}
__device__ __forceinline__ u64 f2add(u64 a, u64 b) {
    u64 d; asm("add.rn.f32x2 %0,%1,%2;" : "=l"(d) : "l"(a), "l"(b)); return d;
}
__device__ __forceinline__ u64 f2mul(u64 a, u64 b) {
    u64 d; asm("mul.rn.f32x2 %0,%1,%2;" : "=l"(d) : "l"(a), "l"(b)); return d;
}
__device__ __forceinline__ void ld2(const float* p, u64& a, u64& b) {
    float4 v = *reinterpret_cast<const float4*>(p);
    a = pk2(v.x, v.y); b = pk2(v.z, v.w);
}

// fast GELU: x * sigmoid(1.5957691*(x + 0.044715*x^3)); max abs err ~1.5e-4
__device__ __forceinline__ float gelu_f(float xv) {
    float t = xv * xv;
    float u = fmaf(t, -0.07135481627f, -1.59576912161f);   // -2*0.79788456*(1+0.044715 t)
    float e = __expf(xv * u);
    return __fdividef(xv, 1.0f + e);
}

// ---- pack kernel: gather 11 param arrays into one __device__ buffer ----
__global__ void pack_kernel(const float* Wk, const float* Wq, const float* Wv,
                            const float* g1, const float* B1,
                            const float* g2, const float* B2,
                            const float* W1, const float* b1,
                            const float* W2, const float* b2)
{
    int i = threadIdx.x;
    if (i < 256) { gPf[OFF_WK + i] = Wk[i]; gPf[OFF_WQ + i] = Wq[i]; gPf[OFF_WV + i] = Wv[i]; }
    for (int j = i; j < 512; j += 256) { gPf[OFF_W1 + j] = W1[j]; gPf[OFF_W2 + j] = W2[j]; }
    if (i < DFF) gPf[OFF_B1 + i] = b1[i];
    if (i < DM) {
        gPf[OFF_B2 + i]  = b2[i];
        gPf[OFF_G1 + i]  = g1[i];
        gPf[OFF_BE1 + i] = B1[i];
        gPf[OFF_G2 + i]  = g2[i];
        gPf[OFF_BE2 + i] = B2[i];
    }
}

// LayerNorm over 16 channels (8 packed pairs), params from constant bank
template <int GOFF, int BOFF>
__device__ __forceinline__ void ln16c(const u64* xp, float* hs)
{
    u64 acc = f2add(f2add(f2add(xp[0], xp[1]), f2add(xp[2], xp[3])),
                    f2add(f2add(xp[4], xp[5]), f2add(xp[6], xp[7])));
    float2 s2 = up2(acc);
    float mu = (s2.x + s2.y) * (1.0f / DM);
    u64 nmu = pk2(-mu, -mu);
    u64 v0 = 0ull, v1 = 0ull;
    #pragma unroll
    for (int i = 0; i < 8; i += 2) {
        u64 d0 = f2add(xp[i], nmu);     v0 = f2fma(d0, d0, v0);
        u64 d1 = f2add(xp[i + 1], nmu); v1 = f2fma(d1, d1, v1);
    }
    s2 = up2(f2add(v0, v1));
    float rstd = rsqrtf((s2.x + s2.y) * (1.0f / DM) + EPSF);
    #pragma unroll
    for (int c = 0; c < DM; c++) {
        float2 xv = up2(xp[c >> 1]);
        float xc = (c & 1) ? xv.y : xv.x;
        hs[c] = (xc - mu) * rstd * cPf[GOFF + c] + cPf[BOFF + c];
    }
}

// 16x16 projection for two tokens from constant weights (flat, compile-time base)
template <int WOFF>
__device__ __forceinline__ void proj2c(const float* hA, const float* hB, u64* aA, u64* aB)
{
    #pragma unroll
    for (int i = 0; i < 8; i++) { aA[i] = 0ull; aB[i] = 0ull; }
    #pragma unroll
    for (int c = 0; c < DM; c++) {
        u64 hbA = pk2(hA[c], hA[c]);
        u64 hbB = pk2(hB[c], hB[c]);
        #pragma unroll
        for (int i = 0; i < 8; i++) {
            u64 wp = pk2(cPf[WOFF + c * DM + 2 * i], cPf[WOFF + c * DM + 2 * i + 1]);
            aA[i] = f2fma(hbA, wp, aA[i]);
            aB[i] = f2fma(hbB, wp, aB[i]);
        }
    }
}

__device__ __forceinline__ void st_row(float* p, const u64* a)
{
    #pragma unroll
    for (int i = 0; i < 4; i++) {
        float2 lo = up2(a[2 * i]), hi = up2(a[2 * i + 1]);
        *reinterpret_cast<float4*>(p + 4 * i) = make_float4(lo.x, lo.y, hi.x, hi.y);
    }
}

__global__ __launch_bounds__(128, 4)
void block_kernel(const float* __restrict__ x, float* __restrict__ out)
{
    __shared__ float sK[4][TT][DM], sV[4][TT][DM];

    const int tid = threadIdx.x;
    const int w   = tid >> 5;          // warp = one batch element
    const int t   = tid & 31;          // token A = t, token B = t + 32
    const long long b = (long long)blockIdx.x * 4 + w;

    // ---- load both token rows ----
    u64 xA[8], xB[8];
    const float* xa = x + (b * TT + t) * DM;
    #pragma unroll
    for (int i = 0; i < 4; i++) {
        float4 v4 = *reinterpret_cast<const float4*>(xa + 4 * i);
        xA[2 * i] = pk2(v4.x, v4.y); xA[2 * i + 1] = pk2(v4.z, v4.w);
        float4 w4 = *reinterpret_cast<const float4*>(xa + 32 * DM + 4 * i);
        xB[2 * i] = pk2(w4.x, w4.y); xB[2 * i + 1] = pk2(w4.z, w4.w);
    }

    // ---- LN1 ----
    float hA[DM], hB[DM];
    ln16c<OFF_G1, OFF_BE1>(xA, hA);
    ln16c<OFF_G1, OFF_BE1>(xB, hB);

    // ---- K, V, Q projections (phased) ----
    {
        u64 aA[8], aB[8];
        proj2c<OFF_WK>(hA, hB, aA, aB);
        st_row(&sK[w][t][0], aA);
        st_row(&sK[w][t + 32][0], aB);
        proj2c<OFF_WV>(hA, hB, aA, aB);
        st_row(&sV[w][t][0], aA);
        st_row(&sV[w][t + 32][0], aB);
    }
    u64 qA[8], qB[8];
    proj2c<OFF_WQ>(hA, hB, qA, qB);
    {
        u64 qt = pk2(0.25f, 0.25f);     // fold 1/sqrt(C)
        #pragma unroll
        for (int i = 0; i < 8; i++) { qA[i] = f2mul(qA[i], qt); qB[i] = f2mul(qB[i], qt); }
    }
    __syncwarp();      // K/V tile is warp-private

    // ---- causal attention: single pass, no max subtraction ----
    float lA = 0.f, lB = 0.f;
    u64 yA[8], yB[8];
    #pragma unroll
    for (int i = 0; i < 8; i++) { yA[i] = 0ull; yB[i] = 0ull; }

    const float (*Kw)[DM] = sK[w];
    const float (*Vw)[DM] = sV[w];

    #pragma unroll
    for (int s = 0; s < 32; s++) {
        u64 kr[8];
        ld2(&Kw[s][0], kr[0], kr[1]); ld2(&Kw[s][4], kr[2], kr[3]);
        ld2(&Kw[s][8], kr[4], kr[5]); ld2(&Kw[s][12], kr[6], kr[7]);
        u64 a0 = 0ull, a1 = 0ull, b0 = 0ull, b1_ = 0ull;
        #pragma unroll
        for (int i = 0; i < 4; i++) {
            a0  = f2fma(qA[2 * i],     kr[2 * i],     a0);
            a1  = f2fma(qA[2 * i + 1], kr[2 * i + 1], a1);
            b0  = f2fma(qB[2 * i],     kr[2 * i],     b0);
            b1_ = f2fma(qB[2 * i + 1], kr[2 * i + 1], b1_);
        }
        float2 fa = up2(f2add(a0, a1)), fb = up2(f2add(b0, b1_));
        float pA = (s <= t) ? __expf(fa.x + fa.y) : 0.f;
        float pB = __expf(fb.x + fb.y);
        lA += pA; lB += pB;
        u64 vr[8];
        ld2(&Vw[s][0], vr[0], vr[1]); ld2(&Vw[s][4], vr[2], vr[3]);
        ld2(&Vw[s][8], vr[4], vr[5]); ld2(&Vw[s][12], vr[6], vr[7]);
        u64 pAp = pk2(pA, pA), pBp = pk2(pB, pB);
        #pragma unroll
        for (int i = 0; i < 8; i++) {
            yA[i] = f2fma(pAp, vr[i], yA[i]);
            yB[i] = f2fma(pBp, vr[i], yB[i]);
        }
    }
    #pragma unroll
    for (int s = 32; s < TT; s++) {
        u64 kr[8];
        ld2(&Kw[s][0], kr[0], kr[1]); ld2(&Kw[s][4], kr[2], kr[3]);
        ld2(&Kw[s][8], kr[4], kr[5]); ld2(&Kw[s][12], kr[6], kr[7]);
        u64 b0 = 0ull, b1_ = 0ull;
        #pragma unroll
        for (int i = 0; i < 4; i++) {
            b0  = f2fma(qB[2 * i],     kr[2 * i],     b0);
            b1_ = f2fma(qB[2 * i + 1], kr[2 * i + 1], b1_);
        }
        float2 fb = up2(f2add(b0, b1_));
        float pB = (t >= s - 32) ? __expf(fb.x + fb.y) : 0.f;
        lB += pB;
        u64 vr[8];
        ld2(&Vw[s][0], vr[0], vr[1]); ld2(&Vw[s][4], vr[2], vr[3]);
        ld2(&Vw[s][8], vr[4], vr[5]); ld2(&Vw[s][12], vr[6], vr[7]);
        u64 pBp = pk2(pB, pB);
        #pragma unroll
        for (int i = 0; i < 8; i++) yB[i] = f2fma(pBp, vr[i], yB[i]);
    }

    {   // residual 1
        float invA = __fdividef(1.0f, lA), invB = __fdividef(1.0f, lB);
        u64 ia = pk2(invA, invA), ib = pk2(invB, invB);
        #pragma unroll
        for (int i = 0; i < 8; i++) {
            xA[i] = f2fma(yA[i], ia, xA[i]);
            xB[i] = f2fma(yB[i], ib, xB[i]);
        }
    }

    // ---- LN2 ----
    ln16c<OFF_G2, OFF_BE2>(xA, hA);
    ln16c<OFF_G2, OFF_BE2>(xB, hB);

    // ---- FFN: dual-token, split over DFF halves (weights loaded once) ----
    u64 oA[8], oB[8];
    #pragma unroll
    for (int i = 0; i < 8; i++) {
        u64 bp = pk2(cPf[OFF_B2 + 2 * i], cPf[OFF_B2 + 2 * i + 1]);
        oA[i] = f2add(xA[i], bp);
        oB[i] = f2add(xB[i], bp);
    }
    #pragma unroll
    for (int half = 0; half < 2; half++) {
        const int HB = half * 16;
        u64 fA[8], fB[8];
        #pragma unroll
        for (int i = 0; i < 8; i++) {
            u64 bp = pk2(cPf[OFF_B1 + HB + 2 * i], cPf[OFF_B1 + HB + 2 * i + 1]);
            fA[i] = bp; fB[i] = bp;
        }
        #pragma unroll
        for (int c = 0; c < DM; c++) {
            u64 hbA = pk2(hA[c], hA[c]);
            u64 hbB = pk2(hB[c], hB[c]);
            #pragma unroll
            for (int i = 0; i < 8; i++) {
                u64 wp = pk2(cPf[OFF_W1 + c * DFF + HB + 2 * i],
                             cPf[OFF_W1 + c * DFF + HB + 2 * i + 1]);
                fA[i] = f2fma(hbA, wp, fA[i]);
                fB[i] = f2fma(hbB, wp, fB[i]);
            }
        }
        float gA[16], gB[16];
        #pragma unroll
        for (int i = 0; i < 8; i++) {
            float2 fa = up2(fA[i]), fb = up2(fB[i]);
            gA[2 * i]     = gelu_f(fa.x);
            gA[2 * i + 1] = gelu_f(fa.y);
            gB[2 * i]     = gelu_f(fb.x);
            gB[2 * i + 1] = gelu_f(fb.y);
        }
        #pragma unroll
        for (int j = 0; j < 16; j++) {
            const int jj = HB + j;
            u64 fbA = pk2(gA[j], gA[j]);
            u64 fbB = pk2(gB[j], gB[j]);
            #pragma unroll
            for (int i = 0; i < 8; i++) {
                u64 wp = pk2(cPf[OFF_W2 + jj * DM + 2 * i],
                             cPf[OFF_W2 + jj * DM + 2 * i + 1]);
                oA[i] = f2fma(fbA, wp, oA[i]);
                oB[i] = f2fma(fbB, wp, oB[i]);
            }
        }
    }

    // ---- store both tokens ----
    float* op = out + (b * TT + t) * DM;
    st_row(op, oA);
    st_row(op + 32 * DM, oB);
}

extern "C" void kernel_launch(void* const* d_in, const int* in_sizes, int n_in,
                              void* d_out, int out_size)
{
    const float* x = (const float*)d_in[0];
    float* out = (float*)d_out;

    // 1) gather all params into one device buffer (one kernel node)
    pack_kernel<<<1, 256>>>((const float*)d_in[1], (const float*)d_in[2],
                            (const float*)d_in[3], (const float*)d_in[4],
                            (const float*)d_in[5], (const float*)d_in[6],
                            (const float*)d_in[7], (const float*)d_in[8],
                            (const float*)d_in[9], (const float*)d_in[10],
                            (const float*)d_in[11]);
    // 2) single D2D copy into the constant bank (one memcpy node)
    void* src = nullptr;
    cudaGetSymbolAddress(&src, gPf);
    cudaMemcpyToSymbolAsync(cPf, src, NPARAM * sizeof(float), 0,
                            cudaMemcpyDeviceToDevice);

    int B = in_sizes[0] / (TT * DM);
    dim3 grid((B + 3) / 4);               // 4 batch elements per CTA (1 per warp)
    block_kernel<<<grid, 128>>>(x, out);
}

// round 7
// speedup vs baseline: 1.1403x; 1.0074x over previous
#include <cuda_runtime.h>
#include <math.h>

#define TT 64
#define DM 16
#define DFF 32
#define EPSF 1e-5f

// flat parameter bank offsets (floats; all even -> 8B aligned pairs)
#define OFF_WK  0
#define OFF_WQ  256
#define OFF_WV  512
#define OFF_W1  768
#define OFF_W2  1280
#define OFF_B1  1792
#define OFF_B2  1824
#define OFF_G1  1840
#define OFF_BE1 1856
#define OFF_G2  1872
#define OFF_BE2 1888
#define NPARAM  1904

__constant__ __align__(16) float cPf[NPARAM];
__device__   __align__(16) float gPf[NPARAM];

typedef unsigned long long u64;

__device__ __forceinline__ u64 pk2(float lo, float hi) {
    u64 r; asm("mov.b64 %0,{%1,%2};" : "=l"(r) : "f"(lo), "f"(hi)); return r;
}
__device__ __forceinline__ float2 up2(u64 v) {
    float2 f; asm("mov.b64 {%0,%1},%2;" : "=f"(f.x), "=f"(f.y) : "l"(v)); return f;
}
__device__ __forceinline__ u64 f2fma(u64 a, u64 b, u64 c) {
    u64 d; asm("fma.rn.f32x2 %0,%1,%2,%3;" : "=l"(d) : "l"(a), "l"(b), "l"(c)); return d;
}
__device__ __forceinline__ u64 f2add(u64 a, u64 b) {
    u64 d; asm("add.rn.f32x2 %0,%1,%2;" : "=l"(d) : "l"(a), "l"(b)); return d;
}
__device__ __forceinline__ u64 f2mul(u64 a, u64 b) {
    u64 d; asm("mul.rn.f32x2 %0,%1,%2;" : "=l"(d) : "l"(a), "l"(b)); return d;
}
// one LDS.128 -> two packed pairs directly (no repacking MOVs)
__device__ __forceinline__ void ld2(const float* p, u64& a, u64& b) {
    ulonglong2 v = *reinterpret_cast<const ulonglong2*>(p);
    a = v.x; b = v.y;
}
// direct 64-bit constant-bank load of a float pair
__device__ __forceinline__ u64 ldc2(int off) {
    return *reinterpret_cast<const u64*>(&cPf[off]);
}
// 16B store of two packed pairs
__device__ __forceinline__ void st2(float* p, u64 a, u64 b) {
    *reinterpret_cast<ulonglong2*>(p) = make_ulonglong2(a, b);
}

// fast GELU: x * sigmoid(1.5957691*(x + 0.044715*x^3)); max abs err ~1.5e-4
__device__ __forceinline__ float gelu_f(float xv) {
    float t = xv * xv;
    float u = fmaf(t, -0.07135481627f, -1.59576912161f);
    float e = __expf(xv * u);
    return __fdividef(xv, 1.0f + e);
}

// ---- pack kernel: gather 11 param arrays into one __device__ buffer ----
__global__ void pack_kernel(const float* Wk, const float* Wq, const float* Wv,
                            const float* g1, const float* B1,
                            const float* g2, const float* B2,
                            const float* W1, const float* b1,
                            const float* W2, const float* b2)
{
    int i = threadIdx.x;
    if (i < 256) { gPf[OFF_WK + i] = Wk[i]; gPf[OFF_WQ + i] = Wq[i]; gPf[OFF_WV + i] = Wv[i]; }
    for (int j = i; j < 512; j += 256) { gPf[OFF_W1 + j] = W1[j]; gPf[OFF_W2 + j] = W2[j]; }
    if (i < DFF) gPf[OFF_B1 + i] = b1[i];
    if (i < DM) {
        gPf[OFF_B2 + i]  = b2[i];
        gPf[OFF_G1 + i]  = g1[i];
        gPf[OFF_BE1 + i] = B1[i];
        gPf[OFF_G2 + i]  = g2[i];
        gPf[OFF_BE2 + i] = B2[i];
    }
}

// LayerNorm over 16 channels (8 packed pairs), params from constant bank
template <int GOFF, int BOFF>
__device__ __forceinline__ void ln16c(const u64* xp, float* hs)
{
    u64 acc = f2add(f2add(f2add(xp[0], xp[1]), f2add(xp[2], xp[3])),
                    f2add(f2add(xp[4], xp[5]), f2add(xp[6], xp[7])));
    float2 s2 = up2(acc);
    float mu = (s2.x + s2.y) * (1.0f / DM);
    u64 nmu = pk2(-mu, -mu);
    u64 v0 = 0ull, v1 = 0ull;
    #pragma unroll
    for (int i = 0; i < 8; i += 2) {
        u64 d0 = f2add(xp[i], nmu);     v0 = f2fma(d0, d0, v0);
        u64 d1 = f2add(xp[i + 1], nmu); v1 = f2fma(d1, d1, v1);
    }
    s2 = up2(f2add(v0, v1));
    float rstd = rsqrtf((s2.x + s2.y) * (1.0f / DM) + EPSF);
    #pragma unroll
    for (int c = 0; c < DM; c++) {
        float2 xv = up2(xp[c >> 1]);
        float xc = (c & 1) ? xv.y : xv.x;
        hs[c] = (xc - mu) * rstd * cPf[GOFF + c] + cPf[BOFF + c];
    }
}

// 16x16 projection for two tokens from constant weights (direct LDC.64)
template <int WOFF>
__device__ __forceinline__ void proj2c(const float* hA, const float* hB, u64* aA, u64* aB)
{
    #pragma unroll
    for (int i = 0; i < 8; i++) { aA[i] = 0ull; aB[i] = 0ull; }
    #pragma unroll
    for (int c = 0; c < DM; c++) {
        u64 hbA = pk2(hA[c], hA[c]);
        u64 hbB = pk2(hB[c], hB[c]);
        #pragma unroll
        for (int i = 0; i < 8; i++) {
            u64 wp = ldc2(WOFF + c * DM + 2 * i);
            aA[i] = f2fma(hbA, wp, aA[i]);
            aB[i] = f2fma(hbB, wp, aB[i]);
        }
    }
}

__device__ __forceinline__ void st_row(float* p, const u64* a)
{
    st2(p,     a[0], a[1]);
    st2(p + 4, a[2], a[3]);
    st2(p + 8, a[4], a[5]);
    st2(p + 12, a[6], a[7]);
}

__global__ __launch_bounds__(128, 4)
void block_kernel(const float* __restrict__ x, float* __restrict__ out)
{
    __shared__ float sK[4][TT][DM], sV[4][TT][DM];

    const int tid = threadIdx.x;
    const int w   = tid >> 5;          // warp = one batch element
    const int t   = tid & 31;          // token A = t, token B = t + 32
    const long long b = (long long)blockIdx.x * 4 + w;

    // ---- load both token rows (LDG.128 -> packed pairs, no MOVs) ----
    u64 xA[8], xB[8];
    const float* xa = x + (b * TT + t) * DM;
    #pragma unroll
    for (int i = 0; i < 4; i++) {
        ulonglong2 v = *reinterpret_cast<const ulonglong2*>(xa + 4 * i);
        xA[2 * i] = v.x; xA[2 * i + 1] = v.y;
        ulonglong2 u = *reinterpret_cast<const ulonglong2*>(xa + 32 * DM + 4 * i);
        xB[2 * i] = u.x; xB[2 * i + 1] = u.y;
    }

    // ---- LN1 ----
    float hA[DM], hB[DM];
    ln16c<OFF_G1, OFF_BE1>(xA, hA);
    ln16c<OFF_G1, OFF_BE1>(xB, hB);

    // ---- K, V, Q projections (phased) ----
    {
        u64 aA[8], aB[8];
        proj2c<OFF_WK>(hA, hB, aA, aB);
        st_row(&sK[w][t][0], aA);
        st_row(&sK[w][t + 32][0], aB);
        proj2c<OFF_WV>(hA, hB, aA, aB);
        st_row(&sV[w][t][0], aA);
        st_row(&sV[w][t + 32][0], aB);
    }
    u64 qA[8], qB[8];
    proj2c<OFF_WQ>(hA, hB, qA, qB);
    {
        u64 qt = pk2(0.25f, 0.25f);     // fold 1/sqrt(C)
        #pragma unroll
        for (int i = 0; i < 8; i++) { qA[i] = f2mul(qA[i], qt); qB[i] = f2mul(qB[i], qt); }
    }
    __syncwarp();      // K/V tile is warp-private

    // ---- causal attention: single pass, no max subtraction ----
    float lA = 0.f, lB = 0.f;
    u64 yA[8], yB[8];
    #pragma unroll
    for (int i = 0; i < 8; i++) { yA[i] = 0ull; yB[i] = 0ull; }

    const float (*Kw)[DM] = sK[w];
    const float (*Vw)[DM] = sV[w];

    #pragma unroll
    for (int s = 0; s < 32; s++) {
        u64 kr[8];
        ld2(&Kw[s][0], kr[0], kr[1]); ld2(&Kw[s][4], kr[2], kr[3]);
        ld2(&Kw[s][8], kr[4], kr[5]); ld2(&Kw[s][12], kr[6], kr[7]);
        u64 a0 = 0ull, a1 = 0ull, b0 = 0ull, b1_ = 0ull;
        #pragma unroll
        for (int i = 0; i < 4; i++) {
            a0  = f2fma(qA[2 * i],     kr[2 * i],     a0);
            a1  = f2fma(qA[2 * i + 1], kr[2 * i + 1], a1);
            b0  = f2fma(qB[2 * i],     kr[2 * i],     b0);
            b1_ = f2fma(qB[2 * i + 1], kr[2 * i + 1], b1_);
        }
        float2 fa = up2(f2add(a0, a1)), fb = up2(f2add(b0, b1_));
        float pA = (s <= t) ? __expf(fa.x + fa.y) : 0.f;
        float pB = __expf(fb.x + fb.y);
        lA += pA; lB += pB;
        u64 vr[8];
        ld2(&Vw[s][0], vr[0], vr[1]); ld2(&Vw[s][4], vr[2], vr[3]);
        ld2(&Vw[s][8], vr[4], vr[5]); ld2(&Vw[s][12], vr[6], vr[7]);
        u64 pAp = pk2(pA, pA), pBp = pk2(pB, pB);
        #pragma unroll
        for (int i = 0; i < 8; i++) {
            yA[i] = f2fma(pAp, vr[i], yA[i]);
            yB[i] = f2fma(pBp, vr[i], yB[i]);
        }
    }
    #pragma unroll
    for (int s = 32; s < TT; s++) {
        u64 kr[8];
        ld2(&Kw[s][0], kr[0], kr[1]); ld2(&Kw[s][4], kr[2], kr[3]);
        ld2(&Kw[s][8], kr[4], kr[5]); ld2(&Kw[s][12], kr[6], kr[7]);
        u64 b0 = 0ull, b1_ = 0ull;
        #pragma unroll
        for (int i = 0; i < 4; i++) {
            b0  = f2fma(qB[2 * i],     kr[2 * i],     b0);
            b1_ = f2fma(qB[2 * i + 1], kr[2 * i + 1], b1_);
        }
        float2 fb = up2(f2add(b0, b1_));
        float pB = (t >= s - 32) ? __expf(fb.x + fb.y) : 0.f;
        lB += pB;
        u64 vr[8];
        ld2(&Vw[s][0], vr[0], vr[1]); ld2(&Vw[s][4], vr[2], vr[3]);
        ld2(&Vw[s][8], vr[4], vr[5]); ld2(&Vw[s][12], vr[6], vr[7]);
        u64 pBp = pk2(pB, pB);
        #pragma unroll
        for (int i = 0; i < 8; i++) yB[i] = f2fma(pBp, vr[i], yB[i]);
    }

    {   // residual 1
        float invA = __fdividef(1.0f, lA), invB = __fdividef(1.0f, lB);
        u64 ia = pk2(invA, invA), ib = pk2(invB, invB);
        #pragma unroll
        for (int i = 0; i < 8; i++) {
            xA[i] = f2fma(yA[i], ia, xA[i]);
            xB[i] = f2fma(yB[i], ib, xB[i]);
        }
    }

    // ---- LN2 ----
    ln16c<OFF_G2, OFF_BE2>(xA, hA);
    ln16c<OFF_G2, OFF_BE2>(xB, hB);

    // ---- FFN: dual-token, split over DFF halves (weights loaded once) ----
    u64 oA[8], oB[8];
    #pragma unroll
    for (int i = 0; i < 8; i++) {
        u64 bp = ldc2(OFF_B2 + 2 * i);
        oA[i] = f2add(xA[i], bp);
        oB[i] = f2add(xB[i], bp);
    }
    #pragma unroll
    for (int half = 0; half < 2; half++) {
        const int HB = half * 16;
        u64 fA[8], fB[8];
        #pragma unroll
        for (int i = 0; i < 8; i++) {
            u64 bp = ldc2(OFF_B1 + HB + 2 * i);
            fA[i] = bp; fB[i] = bp;
        }
        #pragma unroll
        for (int c = 0; c < DM; c++) {
            u64 hbA = pk2(hA[c], hA[c]);
            u64 hbB = pk2(hB[c], hB[c]);
            #pragma unroll
            for (int i = 0; i < 8; i++) {
                u64 wp = ldc2(OFF_W1 + c * DFF + HB + 2 * i);
                fA[i] = f2fma(hbA, wp, fA[i]);
                fB[i] = f2fma(hbB, wp, fB[i]);
            }
        }
        float gA[16], gB[16];
        #pragma unroll
        for (int i = 0; i < 8; i++) {
            float2 fa = up2(fA[i]), fb = up2(fB[i]);
            gA[2 * i]     = gelu_f(fa.x);
            gA[2 * i + 1] = gelu_f(fa.y);
            gB[2 * i]     = gelu_f(fb.x);
            gB[2 * i + 1] = gelu_f(fb.y);
        }
        #pragma unroll
        for (int j = 0; j < 16; j++) {
            const int jj = HB + j;
            u64 fbA = pk2(gA[j], gA[j]);
            u64 fbB = pk2(gB[j], gB[j]);
            #pragma unroll
            for (int i = 0; i < 8; i++) {
                u64 wp = ldc2(OFF_W2 + jj * DM + 2 * i);
                oA[i] = f2fma(fbA, wp, oA[i]);
                oB[i] = f2fma(fbB, wp, oB[i]);
            }
        }
    }

    // ---- store both tokens ----
    float* op = out + (b * TT + t) * DM;
    st_row(op, oA);
    st_row(op + 32 * DM, oB);
}

extern "C" void kernel_launch(void* const* d_in, const int* in_sizes, int n_in,
                              void* d_out, int out_size)
{
    const float* x = (const float*)d_in[0];
    float* out = (float*)d_out;

    // 1) gather all params into one device buffer (one kernel node)
    pack_kernel<<<1, 256>>>((const float*)d_in[1], (const float*)d_in[2],
                            (const float*)d_in[3], (const float*)d_in[4],
                            (const float*)d_in[5], (const float*)d_in[6],
                            (const float*)d_in[7], (const float*)d_in[8],
                            (const float*)d_in[9], (const float*)d_in[10],
                            (const float*)d_in[11]);
    // 2) single D2D copy into the constant bank (one memcpy node)
    void* src = nullptr;
    cudaGetSymbolAddress(&src, gPf);
    cudaMemcpyToSymbolAsync(cPf, src, NPARAM * sizeof(float), 0,
                            cudaMemcpyDeviceToDevice);

    int B = in_sizes[0] / (TT * DM);
    dim3 grid((B + 3) / 4);               // 4 batch elements per CTA (1 per warp)
    block_kernel<<<grid, 128>>>(x, out);
}

// round 8
// speedup vs baseline: 2.0218x; 1.7731x over previous
#include <cuda_runtime.h>
#include <cuda_fp16.h>
#include <math.h>

#define TT 64
#define DM 16
#define DFF 32
#define EPSF 1e-5f

// flat parameter bank offsets (floats; all even -> 8B aligned pairs)
#define OFF_WK  0
#define OFF_WQ  256
#define OFF_WV  512
#define OFF_W1  768
#define OFF_W2  1280
#define OFF_B1  1792
#define OFF_B2  1824
#define OFF_G1  1840
#define OFF_BE1 1856
#define OFF_G2  1872
#define OFF_BE2 1888
#define NPARAM  1904

__constant__ __align__(16) float cPf[NPARAM];
__device__   __align__(16) float gPf[NPARAM];

typedef unsigned long long u64;
typedef unsigned int u32;

// per-warp smem layout (bytes):
//  Q_h  [64 rows][20 halves]  @ 0     (2560)
//  K_h  [64 rows][20 halves]  @ 2560  (2560)
//  V_t  [16 ch ][80 halves]   @ 5120  (2560)   (transposed: row=channel, col=key)
//  y    [64 rows][20 floats]  @ 2560  (5120)   overlays K+V after frags preloaded
//  x    [64 rows][16 floats]  @ 7680  (4096)
#define QOFF 0
#define KOFF 2560
#define VOFF 5120
#define YOFF 2560
#define XOFF 7680
#define WARP_BYTES 11776

__device__ __forceinline__ u64 pk2(float lo, float hi) {
    u64 r; asm("mov.b64 %0,{%1,%2};" : "=l"(r) : "f"(lo), "f"(hi)); return r;
}
__device__ __forceinline__ float2 up2(u64 v) {
    float2 f; asm("mov.b64 {%0,%1},%2;" : "=f"(f.x), "=f"(f.y) : "l"(v)); return f;
}
__device__ __forceinline__ u64 f2fma(u64 a, u64 b, u64 c) {
    u64 d; asm("fma.rn.f32x2 %0,%1,%2,%3;" : "=l"(d) : "l"(a), "l"(b), "l"(c)); return d;
}
__device__ __forceinline__ u64 f2add(u64 a, u64 b) {
    u64 d; asm("add.rn.f32x2 %0,%1,%2;" : "=l"(d) : "l"(a), "l"(b)); return d;
}
__device__ __forceinline__ u64 f2mul(u64 a, u64 b) {
    u64 d; asm("mul.rn.f32x2 %0,%1,%2;" : "=l"(d) : "l"(a), "l"(b)); return d;
}
__device__ __forceinline__ u64 ldc2(int off) {
    return *reinterpret_cast<const u64*>(&cPf[off]);
}
// pack two f32 -> f16x2 (hi, lo)
__device__ __forceinline__ u32 h2(float hi, float lo) {
    u32 r; asm("cvt.rn.f16x2.f32 %0, %1, %2;" : "=r"(r) : "f"(hi), "f"(lo)); return r;
}
// m16n8k16 row.col f16 -> f32 accumulate
__device__ __forceinline__ void mma16816(float& c0, float& c1, float& c2, float& c3,
                                         u32 a0, u32 a1, u32 a2, u32 a3,
                                         u32 b0, u32 b1)
{
    asm volatile("mma.sync.aligned.m16n8k16.row.col.f32.f16.f16.f32 "
                 "{%0,%1,%2,%3}, {%4,%5,%6,%7}, {%8,%9}, {%0,%1,%2,%3};"
                 : "+f"(c0), "+f"(c1), "+f"(c2), "+f"(c3)
                 : "r"(a0), "r"(a1), "r"(a2), "r"(a3), "r"(b0), "r"(b1));
}

// fast GELU
__device__ __forceinline__ float gelu_f(float xv) {
    float t = xv * xv;
    float u = fmaf(t, -0.07135481627f, -1.59576912161f);
    float e = __expf(xv * u);
    return __fdividef(xv, 1.0f + e);
}

__global__ void pack_kernel(const float* Wk, const float* Wq, const float* Wv,
                            const float* g1, const float* B1,
                            const float* g2, const float* B2,
                            const float* W1, const float* b1,
                            const float* W2, const float* b2)
{
    int i = threadIdx.x;
    if (i < 256) { gPf[OFF_WK + i] = Wk[i]; gPf[OFF_WQ + i] = Wq[i]; gPf[OFF_WV + i] = Wv[i]; }
    for (int j = i; j < 512; j += 256) { gPf[OFF_W1 + j] = W1[j]; gPf[OFF_W2 + j] = W2[j]; }
    if (i < DFF) gPf[OFF_B1 + i] = b1[i];
    if (i < DM) {
        gPf[OFF_B2 + i]  = b2[i];
        gPf[OFF_G1 + i]  = g1[i];  gPf[OFF_BE1 + i] = B1[i];
        gPf[OFF_G2 + i]  = g2[i];  gPf[OFF_BE2 + i] = B2[i];
    }
}

template <int GOFF, int BOFF>
__device__ __forceinline__ void ln16c(const u64* xp, float* hs)
{
    u64 acc = f2add(f2add(f2add(xp[0], xp[1]), f2add(xp[2], xp[3])),
                    f2add(f2add(xp[4], xp[5]), f2add(xp[6], xp[7])));
    float2 s2 = up2(acc);
    float mu = (s2.x + s2.y) * (1.0f / DM);
    u64 nmu = pk2(-mu, -mu);
    u64 v0 = 0ull, v1 = 0ull;
    #pragma unroll
    for (int i = 0; i < 8; i += 2) {
        u64 d0 = f2add(xp[i], nmu);     v0 = f2fma(d0, d0, v0);
        u64 d1 = f2add(xp[i + 1], nmu); v1 = f2fma(d1, d1, v1);
    }
    s2 = up2(f2add(v0, v1));
    float rstd = rsqrtf((s2.x + s2.y) * (1.0f / DM) + EPSF);
    #pragma unroll
    for (int c = 0; c < DM; c++) {
        float2 xv = up2(xp[c >> 1]);
        float xc = (c & 1) ? xv.y : xv.x;
        hs[c] = (xc - mu) * rstd * cPf[GOFF + c] + cPf[BOFF + c];
    }
}

template <int WOFF>
__device__ __forceinline__ void proj2c(const float* hA, const float* hB, u64* aA, u64* aB)
{
    #pragma unroll
    for (int i = 0; i < 8; i++) { aA[i] = 0ull; aB[i] = 0ull; }
    #pragma unroll
    for (int c = 0; c < DM; c++) {
        u64 hbA = pk2(hA[c], hA[c]);
        u64 hbB = pk2(hB[c], hB[c]);
        #pragma unroll
        for (int i = 0; i < 8; i++) {
            u64 wp = ldc2(WOFF + c * DM + 2 * i);
            aA[i] = f2fma(hbA, wp, aA[i]);
            aB[i] = f2fma(hbB, wp, aB[i]);
        }
    }
}

// store 16-fp32 row (8 packed pairs) as fp16 row at hp (8B-aligned, 40B stride rows)
__device__ __forceinline__ void st_row_h(char* hp, const u64* a)
{
    #pragma unroll
    for (int i = 0; i < 4; i++) {
        float2 lo = up2(a[2 * i]), hi = up2(a[2 * i + 1]);
        u32 p0 = h2(lo.y, lo.x);
        u32 p1 = h2(hi.y, hi.x);
        *reinterpret_cast<uint2*>(hp + i * 8) = make_uint2(p0, p1);
    }
}
// store 16-fp32 row transposed into V_t (row=channel, 160B stride; col=token)
__device__ __forceinline__ void st_col_h(char* vbase, int tok, const u64* a)
{
    #pragma unroll
    for (int i = 0; i < 8; i++) {
        float2 f = up2(a[i]);
        *reinterpret_cast<__half*>(vbase + (2 * i)     * 160 + tok * 2) = __float2half(f.x);
        *reinterpret_cast<__half*>(vbase + (2 * i + 1) * 160 + tok * 2) = __float2half(f.y);
    }
}

__global__ __launch_bounds__(128, 4)
void block_kernel(const float* __restrict__ x, float* __restrict__ out)
{
    __shared__ __align__(16) char smem[4 * WARP_BYTES];

    const int tid = threadIdx.x;
    const int w   = tid >> 5;
    const int t   = tid & 31;
    const int g   = t >> 2;      // mma groupID (row within tile)
    const int qd  = t & 3;       // quad lane (col pair)
    char* Sb = smem + w * WARP_BYTES;
    const long long b = (long long)blockIdx.x * 4 + w;

    // ---- phase 1: load x, LN1, QKV projections, fp16 staging ----
    {
        u64 xA[8], xB[8];
        const float* xa = x + (b * TT + t) * DM;
        #pragma unroll
        for (int i = 0; i < 4; i++) {
            ulonglong2 v = *reinterpret_cast<const ulonglong2*>(xa + 4 * i);
            xA[2 * i] = v.x; xA[2 * i + 1] = v.y;
            *reinterpret_cast<ulonglong2*>(Sb + XOFF + t * 64 + i * 16) = v;
            ulonglong2 u = *reinterpret_cast<const ulonglong2*>(xa + 32 * DM + 4 * i);
            xB[2 * i] = u.x; xB[2 * i + 1] = u.y;
            *reinterpret_cast<ulonglong2*>(Sb + XOFF + (t + 32) * 64 + i * 16) = u;
        }

        float hA[DM], hB[DM];
        ln16c<OFF_G1, OFF_BE1>(xA, hA);
        ln16c<OFF_G1, OFF_BE1>(xB, hB);

        u64 aA[8], aB[8];
        proj2c<OFF_WK>(hA, hB, aA, aB);
        st_row_h(Sb + KOFF + t * 40, aA);
        st_row_h(Sb + KOFF + (t + 32) * 40, aB);
        proj2c<OFF_WV>(hA, hB, aA, aB);
        st_col_h(Sb + VOFF, t, aA);
        st_col_h(Sb + VOFF, t + 32, aB);
        proj2c<OFF_WQ>(hA, hB, aA, aB);
        {
            u64 qt = pk2(0.25f, 0.25f);   // fold 1/sqrt(C) into Q before fp16
            #pragma unroll
            for (int i = 0; i < 8; i++) { aA[i] = f2mul(aA[i], qt); aB[i] = f2mul(aB[i], qt); }
        }
        st_row_h(Sb + QOFF + t * 40, aA);
        st_row_h(Sb + QOFF + (t + 32) * 40, aB);
    }
    __syncwarp();

    // ---- phase 2: preload K and V fragments into registers ----
    u32 kb0[8], kb1[8];
    #pragma unroll
    for (int j = 0; j < 8; j++) {
        const char* kp = Sb + KOFF + (j * 8 + g) * 40 + qd * 4;
        kb0[j] = *reinterpret_cast<const u32*>(kp);
        kb1[j] = *reinterpret_cast<const u32*>(kp + 16);
    }
    u32 vb0[4][2], vb1[4][2];
    #pragma unroll
    for (int s = 0; s < 4; s++) {
        #pragma unroll
        for (int nt = 0; nt < 2; nt++) {
            const char* vp = Sb + VOFF + (nt * 8 + g) * 160 + s * 32 + qd * 4;
            vb0[s][nt] = *reinterpret_cast<const u32*>(vp);
            vb1[s][nt] = *reinterpret_cast<const u32*>(vp + 16);
        }
    }
    __syncwarp();   // K/V regs captured before y overlays their smem

    // ---- phase 3: attention via mma, M-tiles of 16 rows ----
    #pragma unroll
    for (int m = 0; m < 4; m++) {
        const int r0 = m * 16 + g, r1 = r0 + 8;
        const char* qp0 = Sb + QOFF + r0 * 40 + qd * 4;
        const char* qp1 = Sb + QOFF + r1 * 40 + qd * 4;
        u32 qa0 = *reinterpret_cast<const u32*>(qp0);
        u32 qa1 = *reinterpret_cast<const u32*>(qp1);
        u32 qa2 = *reinterpret_cast<const u32*>(qp0 + 16);
        u32 qa3 = *reinterpret_cast<const u32*>(qp1 + 16);

        float e[8][4];
        float l0 = 0.f, l1 = 0.f;
        #pragma unroll
        for (int j = 0; j < 8; j++) {
            if (j > 2 * m + 1) continue;            // fully-future tiles pruned
            float c0 = 0.f, c1 = 0.f, c2 = 0.f, c3 = 0.f;
            mma16816(c0, c1, c2, c3, qa0, qa1, qa2, qa3, kb0[j], kb1[j]);
            int col = j * 8 + 2 * qd;
            e[j][0] = (col     <= r0) ? __expf(c0) : 0.f;
            e[j][1] = (col + 1 <= r0) ? __expf(c1) : 0.f;
            e[j][2] = (col     <= r1) ? __expf(c2) : 0.f;
            e[j][3] = (col + 1 <= r1) ? __expf(c3) : 0.f;
            l0 += e[j][0] + e[j][1];
            l1 += e[j][2] + e[j][3];
        }
        l0 += __shfl_xor_sync(0xffffffff, l0, 1);
        l0 += __shfl_xor_sync(0xffffffff, l0, 2);
        l1 += __shfl_xor_sync(0xffffffff, l1, 1);
        l1 += __shfl_xor_sync(0xffffffff, l1, 2);
        float inv0 = __fdividef(1.0f, l0), inv1 = __fdividef(1.0f, l1);

        // P fragments (A-layout) straight from S accumulators
        u32 pa[4][4];
        #pragma unroll
        for (int s = 0; s < 4; s++) {
            if (s > m) continue;
            pa[s][0] = h2(e[2 * s][1],     e[2 * s][0]);
            pa[s][1] = h2(e[2 * s][3],     e[2 * s][2]);
            pa[s][2] = h2(e[2 * s + 1][1], e[2 * s + 1][0]);
            pa[s][3] = h2(e[2 * s + 1][3], e[2 * s + 1][2]);
        }
        #pragma unroll
        for (int nt = 0; nt < 2; nt++) {
            float y0 = 0.f, y1 = 0.f, y2 = 0.f, y3 = 0.f;
            #pragma unroll
            for (int s = 0; s < 4; s++) {
                if (s > m) continue;
                mma16816(y0, y1, y2, y3,
                         pa[s][0], pa[s][1], pa[s][2], pa[s][3],
                         vb0[s][nt], vb1[s][nt]);
            }
            float* yp0 = reinterpret_cast<float*>(Sb + YOFF + r0 * 80 + (nt * 8 + 2 * qd) * 4);
            float* yp1 = reinterpret_cast<float*>(Sb + YOFF + r1 * 80 + (nt * 8 + 2 * qd) * 4);
            *reinterpret_cast<float2*>(yp0) = make_float2(y0 * inv0, y1 * inv0);
            *reinterpret_cast<float2*>(yp1) = make_float2(y2 * inv1, y3 * inv1);
        }
    }
    __syncwarp();

    // ---- phase 4: residual + LN2 + FFN (scalar, dual-token) ----
    u64 xA[8], xB[8];
    {
        const char* xs = Sb + XOFF + t * 64;
        const char* xs2 = Sb + XOFF + (t + 32) * 64;
        const char* ys = Sb + YOFF + t * 80;
        const char* ys2 = Sb + YOFF + (t + 32) * 80;
        #pragma unroll
        for (int i = 0; i < 4; i++) {
            ulonglong2 vx = *reinterpret_cast<const ulonglong2*>(xs + i * 16);
            ulonglong2 vy = *reinterpret_cast<const ulonglong2*>(ys + i * 16);
            xA[2 * i]     = f2add(vx.x, vy.x);
            xA[2 * i + 1] = f2add(vx.y, vy.y);
            ulonglong2 ux = *reinterpret_cast<const ulonglong2*>(xs2 + i * 16);
            ulonglong2 uy = *reinterpret_cast<const ulonglong2*>(ys2 + i * 16);
            xB[2 * i]     = f2add(ux.x, uy.x);
            xB[2 * i + 1] = f2add(ux.y, uy.y);
        }
    }

    float hA[DM], hB[DM];
    ln16c<OFF_G2, OFF_BE2>(xA, hA);
    ln16c<OFF_G2, OFF_BE2>(xB, hB);

    u64 oA[8], oB[8];
    #pragma unroll
    for (int i = 0; i < 8; i++) {
        u64 bp = ldc2(OFF_B2 + 2 * i);
        oA[i] = f2add(xA[i], bp);
        oB[i] = f2add(xB[i], bp);
    }
    #pragma unroll
    for (int half = 0; half < 2; half++) {
        const int HB = half * 16;
        u64 fA[8], fB[8];
        #pragma unroll
        for (int i = 0; i < 8; i++) {
            u64 bp = ldc2(OFF_B1 + HB + 2 * i);
            fA[i] = bp; fB[i] = bp;
        }
        #pragma unroll
        for (int c = 0; c < DM; c++) {
            u64 hbA = pk2(hA[c], hA[c]);
            u64 hbB = pk2(hB[c], hB[c]);
            #pragma unroll
            for (int i = 0; i < 8; i++) {
                u64 wp = ldc2(OFF_W1 + c * DFF + HB + 2 * i);
                fA[i] = f2fma(hbA, wp, fA[i]);
                fB[i] = f2fma(hbB, wp, fB[i]);
            }
        }
        float gA[16], gB[16];
        #pragma unroll
        for (int i = 0; i < 8; i++) {
            float2 fa = up2(fA[i]), fb = up2(fB[i]);
            gA[2 * i]     = gelu_f(fa.x);
            gA[2 * i + 1] = gelu_f(fa.y);
            gB[2 * i]     = gelu_f(fb.x);
            gB[2 * i + 1] = gelu_f(fb.y);
        }
        #pragma unroll
        for (int j = 0; j < 16; j++) {
            const int jj = HB + j;
            u64 fbA = pk2(gA[j], gA[j]);
            u64 fbB = pk2(gB[j], gB[j]);
            #pragma unroll
            for (int i = 0; i < 8; i++) {
                u64 wp = ldc2(OFF_W2 + jj * DM + 2 * i);
                oA[i] = f2fma(fbA, wp, oA[i]);
                oB[i] = f2fma(fbB, wp, oB[i]);
            }
        }
    }

    float* op = out + (b * TT + t) * DM;
    #pragma unroll
    for (int i = 0; i < 4; i++) {
        *reinterpret_cast<ulonglong2*>(op + 4 * i) =
            make_ulonglong2(oA[2 * i], oA[2 * i + 1]);
        *reinterpret_cast<ulonglong2*>(op + 32 * DM + 4 * i) =
            make_ulonglong2(oB[2 * i], oB[2 * i + 1]);
    }
}

extern "C" void kernel_launch(void* const* d_in, const int* in_sizes, int n_in,
                              void* d_out, int out_size)
{
    const float* x = (const float*)d_in[0];
    float* out = (float*)d_out;

    pack_kernel<<<1, 256>>>((const float*)d_in[1], (const float*)d_in[2],
                            (const float*)d_in[3], (const float*)d_in[4],
                            (const float*)d_in[5], (const float*)d_in[6],
                            (const float*)d_in[7], (const float*)d_in[8],
                            (const float*)d_in[9], (const float*)d_in[10],
                            (const float*)d_in[11]);
    void* src = nullptr;
    cudaGetSymbolAddress(&src, gPf);
    cudaMemcpyToSymbolAsync(cPf, src, NPARAM * sizeof(float), 0,
                            cudaMemcpyDeviceToDevice);

    int B = in_sizes[0] / (TT * DM);
    dim3 grid((B + 3) / 4);
    block_kernel<<<grid, 128>>>(x, out);
}

// round 9
// speedup vs baseline: 2.9737x; 1.4708x over previous
#include <cuda_runtime.h>
#include <cuda_fp16.h>
#include <math.h>

#define TT 64
#define DM 16
#define DFF 32
#define EPSF 1e-5f

// flat parameter bank offsets (floats)
#define OFF_WK  0
#define OFF_WQ  256
#define OFF_WV  512
#define OFF_W1  768
#define OFF_W2  1280
#define OFF_B1  1792
#define OFF_B2  1824
#define OFF_G1  1840
#define OFF_BE1 1856
#define OFF_G2  1872
#define OFF_BE2 1888
#define NPARAM  1904

__constant__ __align__(16) float cPf[NPARAM];
__device__   __align__(16) float gPf[NPARAM];

typedef unsigned long long u64;
typedef unsigned int u32;

// Precomputed fp16 B-fragments (m16n8k16 layout), per-lane tables
__device__ __align__(16) uint2 gFK[2][32];        // K proj, 2 n-tiles
__device__ __align__(16) uint2 gFQ[2][32];        // Q proj (x0.25 folded)
__device__ __align__(16) uint2 gFV[2][32];        // V proj
__device__ __align__(16) uint2 gFW1[4][32];       // FFN1, 4 n-tiles
__device__ __align__(16) uint2 gFW2[2][2][32];    // FFN2, [kstep][ntile]

// per-warp smem layout (bytes):
//  H/Q  [64 rows][20 halves] @ 0     (2560)  h1 rows, then Q rows, then h2 rows
//  K_h  [64 rows][20 halves] @ 2560  (2560)
//  V_t  [16 ch ][80 halves]  @ 5120  (2560)
//  y    [64 rows][20 floats] @ 2560  (5120)  overlays K+V after frag preload
//  x    [64 rows][16 floats] @ 7680  (4096)  x rows, then (x'+b2) rows
#define HOFF 0
#define KOFF 2560
#define VOFF 5120
#define YOFF 2560
#define XOFF 7680
#define WARP_BYTES 11776

__device__ __forceinline__ u64 pk2(float lo, float hi) {
    u64 r; asm("mov.b64 %0,{%1,%2};" : "=l"(r) : "f"(lo), "f"(hi)); return r;
}
__device__ __forceinline__ float2 up2(u64 v) {
    float2 f; asm("mov.b64 {%0,%1},%2;" : "=f"(f.x), "=f"(f.y) : "l"(v)); return f;
}
__device__ __forceinline__ u64 f2fma(u64 a, u64 b, u64 c) {
    u64 d; asm("fma.rn.f32x2 %0,%1,%2,%3;" : "=l"(d) : "l"(a), "l"(b), "l"(c)); return d;
}
__device__ __forceinline__ u64 f2add(u64 a, u64 b) {
    u64 d; asm("add.rn.f32x2 %0,%1,%2;" : "=l"(d) : "l"(a), "l"(b)); return d;
}
__device__ __forceinline__ u64 ldc2(int off) {
    return *reinterpret_cast<const u64*>(&cPf[off]);
}
// pack two f32 -> f16x2 (arg order: hi half, lo half)
__device__ __forceinline__ u32 h2(float hi, float lo) {
    u32 r; asm("cvt.rn.f16x2.f32 %0, %1, %2;" : "=r"(r) : "f"(hi), "f"(lo)); return r;
}
// m16n8k16 row.col f16 -> f32 accumulate
__device__ __forceinline__ void mma16816(float& c0, float& c1, float& c2, float& c3,
                                         u32 a0, u32 a1, u32 a2, u32 a3,
                                         u32 b0, u32 b1)
{
    asm volatile("mma.sync.aligned.m16n8k16.row.col.f32.f16.f16.f32 "
                 "{%0,%1,%2,%3}, {%4,%5,%6,%7}, {%8,%9}, {%0,%1,%2,%3};"
                 : "+f"(c0), "+f"(c1), "+f"(c2), "+f"(c3)
                 : "r"(a0), "r"(a1), "r"(a2), "r"(a3), "r"(b0), "r"(b1));
}

// fast GELU
__device__ __forceinline__ float gelu_f(float xv) {
    float t = xv * xv;
    float u = fmaf(t, -0.07135481627f, -1.59576912161f);
    float e = __expf(xv * u);
    return __fdividef(xv, 1.0f + e);
}

// ---- pack kernel: scalar params + fp16 B-fragment tables ----
__global__ void pack_kernel(const float* Wk, const float* Wq, const float* Wv,
                            const float* g1, const float* B1,
                            const float* g2, const float* B2,
                            const float* W1, const float* b1,
                            const float* W2, const float* b2)
{
    int i = threadIdx.x;
    if (i < 256) { gPf[OFF_WK + i] = Wk[i]; gPf[OFF_WQ + i] = Wq[i]; gPf[OFF_WV + i] = Wv[i]; }
    for (int j = i; j < 512; j += 256) { gPf[OFF_W1 + j] = W1[j]; gPf[OFF_W2 + j] = W2[j]; }
    if (i < DFF) gPf[OFF_B1 + i] = b1[i];
    if (i < DM) {
        gPf[OFF_B2 + i]  = b2[i];
        gPf[OFF_G1 + i]  = g1[i];  gPf[OFF_BE1 + i] = B1[i];
        gPf[OFF_G2 + i]  = g2[i];  gPf[OFF_BE2 + i] = B2[i];
    }

    int lane = i & 31;
    int qd = lane & 3, g = lane >> 2;
    // QKV projection fragments: B[k=c][n=j], W stored [c][j] stride DM
    if (i < 192) {
        int wsel = i >> 6, nt = (i >> 5) & 1;
        const float* W = (wsel == 0) ? Wk : (wsel == 1) ? Wq : Wv;
        float sc = (wsel == 1) ? 0.25f : 1.0f;   // fold 1/sqrt(C) into Wq
        int j = nt * 8 + g;
        uint2 fr;
        fr.x = h2(sc * W[(2*qd+1)*DM + j], sc * W[(2*qd  )*DM + j]);
        fr.y = h2(sc * W[(2*qd+9)*DM + j], sc * W[(2*qd+8)*DM + j]);
        if (wsel == 0) gFK[nt][lane] = fr;
        else if (wsel == 1) gFQ[nt][lane] = fr;
        else gFV[nt][lane] = fr;
    }
    // FFN1 fragments: W1 [c][j] stride DFF
    if (i < 128) {
        int nt = i >> 5;
        int j = nt * 8 + g;
        uint2 fr;
        fr.x = h2(W1[(2*qd+1)*DFF + j], W1[(2*qd  )*DFF + j]);
        fr.y = h2(W1[(2*qd+9)*DFF + j], W1[(2*qd+8)*DFF + j]);
        gFW1[nt][lane] = fr;
    }
    // FFN2 fragments: W2 [c][j] stride DM, K=32 -> 2 ksteps
    if (i < 128) {
        int ks = i >> 6, nt = (i >> 5) & 1;
        int j = nt * 8 + g;
        int kb = ks * 16;
        uint2 fr;
        fr.x = h2(W2[(kb+2*qd+1)*DM + j], W2[(kb+2*qd  )*DM + j]);
        fr.y = h2(W2[(kb+2*qd+9)*DM + j], W2[(kb+2*qd+8)*DM + j]);
        gFW2[ks][nt][lane] = fr;
    }
}

template <int GOFF, int BOFF>
__device__ __forceinline__ void ln16c(const u64* xp, float* hs)
{
    u64 acc = f2add(f2add(f2add(xp[0], xp[1]), f2add(xp[2], xp[3])),
                    f2add(f2add(xp[4], xp[5]), f2add(xp[6], xp[7])));
    float2 s2 = up2(acc);
    float mu = (s2.x + s2.y) * (1.0f / DM);
    u64 nmu = pk2(-mu, -mu);
    u64 v0 = 0ull, v1 = 0ull;
    #pragma unroll
    for (int i = 0; i < 8; i += 2) {
        u64 d0 = f2add(xp[i], nmu);     v0 = f2fma(d0, d0, v0);
        u64 d1 = f2add(xp[i + 1], nmu); v1 = f2fma(d1, d1, v1);
    }
    s2 = up2(f2add(v0, v1));
    float rstd = rsqrtf((s2.x + s2.y) * (1.0f / DM) + EPSF);
    #pragma unroll
    for (int c = 0; c < DM; c++) {
        float2 xv = up2(xp[c >> 1]);
        float xc = (c & 1) ? xv.y : xv.x;
        hs[c] = (xc - mu) * rstd * cPf[GOFF + c] + cPf[BOFF + c];
    }
}

// store 16 scalar f32 as fp16 row (40B-stride region)
__device__ __forceinline__ void st_row_h16(char* hp, const float* hs)
{
    #pragma unroll
    for (int i = 0; i < 4; i++) {
        u32 p0 = h2(hs[4 * i + 1], hs[4 * i]);
        u32 p1 = h2(hs[4 * i + 3], hs[4 * i + 2]);
        *reinterpret_cast<uint2*>(hp + i * 8) = make_uint2(p0, p1);
    }
}

__global__ __launch_bounds__(128, 4)
void block_kernel(const float* __restrict__ x, float* __restrict__ out)
{
    __shared__ __align__(16) char smem[4 * WARP_BYTES];

    const int tid = threadIdx.x;
    const int w   = tid >> 5;
    const int t   = tid & 31;
    const int g   = t >> 2;
    const int qd  = t & 3;
    char* Sb = smem + w * WARP_BYTES;
    const long long b = (long long)blockIdx.x * 4 + w;

    // ---- phase 1: load x, LN1, stage h1 fp16 rows + x rows ----
    {
        u64 xA[8], xB[8];
        const float* xa = x + (b * TT + t) * DM;
        #pragma unroll
        for (int i = 0; i < 4; i++) {
            ulonglong2 v = *reinterpret_cast<const ulonglong2*>(xa + 4 * i);
            xA[2 * i] = v.x; xA[2 * i + 1] = v.y;
            *reinterpret_cast<ulonglong2*>(Sb + XOFF + t * 64 + i * 16) = v;
            ulonglong2 u = *reinterpret_cast<const ulonglong2*>(xa + 32 * DM + 4 * i);
            xB[2 * i] = u.x; xB[2 * i + 1] = u.y;
            *reinterpret_cast<ulonglong2*>(Sb + XOFF + (t + 32) * 64 + i * 16) = u;
        }
        float hA[DM], hB[DM];
        ln16c<OFF_G1, OFF_BE1>(xA, hA);
        ln16c<OFF_G1, OFF_BE1>(xB, hB);
        st_row_h16(Sb + HOFF + t * 40, hA);
        st_row_h16(Sb + HOFF + (t + 32) * 40, hB);
    }
    __syncwarp();

    // ---- phase 2: QKV projections via MMA ----
    u32 ha[4][4];
    #pragma unroll
    for (int m = 0; m < 4; m++) {
        const char* hp0 = Sb + HOFF + (m * 16 + g) * 40 + qd * 4;
        const char* hp1 = Sb + HOFF + (m * 16 + g + 8) * 40 + qd * 4;
        ha[m][0] = *reinterpret_cast<const u32*>(hp0);
        ha[m][1] = *reinterpret_cast<const u32*>(hp1);
        ha[m][2] = *reinterpret_cast<const u32*>(hp0 + 16);
        ha[m][3] = *reinterpret_cast<const u32*>(hp1 + 16);
    }
    uint2 fq0 = gFQ[0][t], fq1 = gFQ[1][t];
    uint2 fk0 = gFK[0][t], fk1 = gFK[1][t];
    uint2 fv0 = gFV[0][t], fv1 = gFV[1][t];
    __syncwarp();   // all h1 reads done before Q overlays HOFF

    #pragma unroll
    for (int m = 0; m < 4; m++) {
        const int r0 = m * 16 + g;
        // Q (scale folded into weights)
        {
            float c0=0,c1=0,c2=0,c3=0, d0=0,d1=0,d2=0,d3=0;
            mma16816(c0,c1,c2,c3, ha[m][0],ha[m][1],ha[m][2],ha[m][3], fq0.x,fq0.y);
            mma16816(d0,d1,d2,d3, ha[m][0],ha[m][1],ha[m][2],ha[m][3], fq1.x,fq1.y);
            char* q0 = Sb + HOFF + r0 * 40;
            char* q1 = Sb + HOFF + (r0 + 8) * 40;
            *reinterpret_cast<u32*>(q0 + qd * 4)      = h2(c1, c0);
            *reinterpret_cast<u32*>(q1 + qd * 4)      = h2(c3, c2);
            *reinterpret_cast<u32*>(q0 + 16 + qd * 4) = h2(d1, d0);
            *reinterpret_cast<u32*>(q1 + 16 + qd * 4) = h2(d3, d2);
        }
        // K
        {
            float c0=0,c1=0,c2=0,c3=0, d0=0,d1=0,d2=0,d3=0;
            mma16816(c0,c1,c2,c3, ha[m][0],ha[m][1],ha[m][2],ha[m][3], fk0.x,fk0.y);
            mma16816(d0,d1,d2,d3, ha[m][0],ha[m][1],ha[m][2],ha[m][3], fk1.x,fk1.y);
            char* k0 = Sb + KOFF + r0 * 40;
            char* k1 = Sb + KOFF + (r0 + 8) * 40;
            *reinterpret_cast<u32*>(k0 + qd * 4)      = h2(c1, c0);
            *reinterpret_cast<u32*>(k1 + qd * 4)      = h2(c3, c2);
            *reinterpret_cast<u32*>(k0 + 16 + qd * 4) = h2(d1, d0);
            *reinterpret_cast<u32*>(k1 + 16 + qd * 4) = h2(d3, d2);
        }
        // V -> transposed V_t [channel][token], 80-half stride
        {
            float c0=0,c1=0,c2=0,c3=0, d0=0,d1=0,d2=0,d3=0;
            mma16816(c0,c1,c2,c3, ha[m][0],ha[m][1],ha[m][2],ha[m][3], fv0.x,fv0.y);
            mma16816(d0,d1,d2,d3, ha[m][0],ha[m][1],ha[m][2],ha[m][3], fv1.x,fv1.y);
            __half* vt = reinterpret_cast<__half*>(Sb + VOFF);
            vt[(2*qd    ) * 80 + r0    ] = __float2half(c0);
            vt[(2*qd + 1) * 80 + r0    ] = __float2half(c1);
            vt[(2*qd    ) * 80 + r0 + 8] = __float2half(c2);
            vt[(2*qd + 1) * 80 + r0 + 8] = __float2half(c3);
            vt[(8 + 2*qd    ) * 80 + r0    ] = __float2half(d0);
            vt[(8 + 2*qd + 1) * 80 + r0    ] = __float2half(d1);
            vt[(8 + 2*qd    ) * 80 + r0 + 8] = __float2half(d2);
            vt[(8 + 2*qd + 1) * 80 + r0 + 8] = __float2half(d3);
        }
    }
    __syncwarp();

    // ---- preload K and V B-fragments into registers ----
    u32 kb0[8], kb1[8];
    #pragma unroll
    for (int j = 0; j < 8; j++) {
        const char* kp = Sb + KOFF + (j * 8 + g) * 40 + qd * 4;
        kb0[j] = *reinterpret_cast<const u32*>(kp);
        kb1[j] = *reinterpret_cast<const u32*>(kp + 16);
    }
    u32 vb0[4][2], vb1[4][2];
    #pragma unroll
    for (int s = 0; s < 4; s++) {
        #pragma unroll
        for (int nt = 0; nt < 2; nt++) {
            const char* vp = Sb + VOFF + (nt * 8 + g) * 160 + s * 32 + qd * 4;
            vb0[s][nt] = *reinterpret_cast<const u32*>(vp);
            vb1[s][nt] = *reinterpret_cast<const u32*>(vp + 16);
        }
    }
    __syncwarp();   // K/V regs captured before y overlays their smem

    // ---- phase 3: attention via MMA ----
    #pragma unroll
    for (int m = 0; m < 4; m++) {
        const int r0 = m * 16 + g, r1 = r0 + 8;
        const char* qp0 = Sb + HOFF + r0 * 40 + qd * 4;
        const char* qp1 = Sb + HOFF + r1 * 40 + qd * 4;
        u32 qa0 = *reinterpret_cast<const u32*>(qp0);
        u32 qa1 = *reinterpret_cast<const u32*>(qp1);
        u32 qa2 = *reinterpret_cast<const u32*>(qp0 + 16);
        u32 qa3 = *reinterpret_cast<const u32*>(qp1 + 16);

        float e[8][4];
        float l0 = 0.f, l1 = 0.f;
        #pragma unroll
        for (int j = 0; j < 8; j++) {
            if (j > 2 * m + 1) continue;
            float c0 = 0.f, c1 = 0.f, c2 = 0.f, c3 = 0.f;
            mma16816(c0, c1, c2, c3, qa0, qa1, qa2, qa3, kb0[j], kb1[j]);
            int col = j * 8 + 2 * qd;
            e[j][0] = (col     <= r0) ? __expf(c0) : 0.f;
            e[j][1] = (col + 1 <= r0) ? __expf(c1) : 0.f;
            e[j][2] = (col     <= r1) ? __expf(c2) : 0.f;
            e[j][3] = (col + 1 <= r1) ? __expf(c3) : 0.f;
            l0 += e[j][0] + e[j][1];
            l1 += e[j][2] + e[j][3];
        }
        l0 += __shfl_xor_sync(0xffffffff, l0, 1);
        l0 += __shfl_xor_sync(0xffffffff, l0, 2);
        l1 += __shfl_xor_sync(0xffffffff, l1, 1);
        l1 += __shfl_xor_sync(0xffffffff, l1, 2);
        float inv0 = __fdividef(1.0f, l0), inv1 = __fdividef(1.0f, l1);

        u32 pa[4][4];
        #pragma unroll
        for (int s = 0; s < 4; s++) {
            if (s > m) continue;
            pa[s][0] = h2(e[2 * s][1],     e[2 * s][0]);
            pa[s][1] = h2(e[2 * s][3],     e[2 * s][2]);
            pa[s][2] = h2(e[2 * s + 1][1], e[2 * s + 1][0]);
            pa[s][3] = h2(e[2 * s + 1][3], e[2 * s + 1][2]);
        }
        #pragma unroll
        for (int nt = 0; nt < 2; nt++) {
            float y0 = 0.f, y1 = 0.f, y2 = 0.f, y3 = 0.f;
            #pragma unroll
            for (int s = 0; s < 4; s++) {
                if (s > m) continue;
                mma16816(y0, y1, y2, y3,
                         pa[s][0], pa[s][1], pa[s][2], pa[s][3],
                         vb0[s][nt], vb1[s][nt]);
            }
            float* yp0 = reinterpret_cast<float*>(Sb + YOFF + r0 * 80 + (nt * 8 + 2 * qd) * 4);
            float* yp1 = reinterpret_cast<float*>(Sb + YOFF + r1 * 80 + (nt * 8 + 2 * qd) * 4);
            *reinterpret_cast<float2*>(yp0) = make_float2(y0 * inv0, y1 * inv0);
            *reinterpret_cast<float2*>(yp1) = make_float2(y2 * inv1, y3 * inv1);
        }
    }
    __syncwarp();

    // ---- phase 4: residual + LN2 (scalar), stage h2 fp16 + (x'+b2) rows ----
    {
        u64 xA[8], xB[8];
        const char* xs  = Sb + XOFF + t * 64;
        const char* xs2 = Sb + XOFF + (t + 32) * 64;
        const char* ys  = Sb + YOFF + t * 80;
        const char* ys2 = Sb + YOFF + (t + 32) * 80;
        #pragma unroll
        for (int i = 0; i < 4; i++) {
            ulonglong2 vx = *reinterpret_cast<const ulonglong2*>(xs + i * 16);
            ulonglong2 vy = *reinterpret_cast<const ulonglong2*>(ys + i * 16);
            xA[2 * i]     = f2add(vx.x, vy.x);
            xA[2 * i + 1] = f2add(vx.y, vy.y);
            ulonglong2 ux = *reinterpret_cast<const ulonglong2*>(xs2 + i * 16);
            ulonglong2 uy = *reinterpret_cast<const ulonglong2*>(ys2 + i * 16);
            xB[2 * i]     = f2add(ux.x, uy.x);
            xB[2 * i + 1] = f2add(ux.y, uy.y);
        }
        float hA[DM], hB[DM];
        ln16c<OFF_G2, OFF_BE2>(xA, hA);
        ln16c<OFF_G2, OFF_BE2>(xB, hB);
        st_row_h16(Sb + HOFF + t * 40, hA);
        st_row_h16(Sb + HOFF + (t + 32) * 40, hB);
        // x'' = x' + b2 back to XOFF
        #pragma unroll
        for (int i = 0; i < 8; i++) {
            u64 bp = ldc2(OFF_B2 + 2 * i);
            xA[i] = f2add(xA[i], bp);
            xB[i] = f2add(xB[i], bp);
        }
        #pragma unroll
        for (int i = 0; i < 4; i++) {
            *reinterpret_cast<ulonglong2*>(Sb + XOFF + t * 64 + i * 16) =
                make_ulonglong2(xA[2 * i], xA[2 * i + 1]);
            *reinterpret_cast<ulonglong2*>(Sb + XOFF + (t + 32) * 64 + i * 16) =
                make_ulonglong2(xB[2 * i], xB[2 * i + 1]);
        }
    }
    __syncwarp();

    // ---- phase 5: FFN via MMA ----
    uint2 w1f[4] = { gFW1[0][t], gFW1[1][t], gFW1[2][t], gFW1[3][t] };
    uint2 w2f[2][2] = { { gFW2[0][0][t], gFW2[0][1][t] },
                        { gFW2[1][0][t], gFW2[1][1][t] } };
    float2 b1v[4];
    #pragma unroll
    for (int nt = 0; nt < 4; nt++)
        b1v[nt] = make_float2(cPf[OFF_B1 + nt * 8 + 2 * qd],
                              cPf[OFF_B1 + nt * 8 + 2 * qd + 1]);

    #pragma unroll
    for (int m = 0; m < 4; m++) {
        const int r0 = m * 16 + g;
        const char* hp0 = Sb + HOFF + r0 * 40 + qd * 4;
        const char* hp1 = Sb + HOFF + (r0 + 8) * 40 + qd * 4;
        u32 a0 = *reinterpret_cast<const u32*>(hp0);
        u32 a1 = *reinterpret_cast<const u32*>(hp1);
        u32 a2 = *reinterpret_cast<const u32*>(hp0 + 16);
        u32 a3 = *reinterpret_cast<const u32*>(hp1 + 16);

        float gl[4][4];
        #pragma unroll
        for (int nt = 0; nt < 4; nt++) {
            float c0 = b1v[nt].x, c1 = b1v[nt].y, c2 = b1v[nt].x, c3 = b1v[nt].y;
            mma16816(c0, c1, c2, c3, a0, a1, a2, a3, w1f[nt].x, w1f[nt].y);
            gl[nt][0] = gelu_f(c0); gl[nt][1] = gelu_f(c1);
            gl[nt][2] = gelu_f(c2); gl[nt][3] = gelu_f(c3);
        }
        // FFN2 A-fragments from gelu'd C-frags (C->A identity)
        u32 p00 = h2(gl[0][1], gl[0][0]), p01 = h2(gl[0][3], gl[0][2]);
        u32 p02 = h2(gl[1][1], gl[1][0]), p03 = h2(gl[1][3], gl[1][2]);
        u32 p10 = h2(gl[2][1], gl[2][0]), p11 = h2(gl[2][3], gl[2][2]);
        u32 p12 = h2(gl[3][1], gl[3][0]), p13 = h2(gl[3][3], gl[3][2]);

        #pragma unroll
        for (int nt = 0; nt < 2; nt++) {
            const int cb = nt * 8 + 2 * qd;
            float2 d0 = *reinterpret_cast<const float2*>(Sb + XOFF + r0 * 64 + cb * 4);
            float2 d1 = *reinterpret_cast<const float2*>(Sb + XOFF + (r0 + 8) * 64 + cb * 4);
            float c0 = d0.x, c1 = d0.y, c2 = d1.x, c3 = d1.y;
            mma16816(c0, c1, c2, c3, p00, p01, p02, p03, w2f[0][nt].x, w2f[0][nt].y);
            mma16816(c0, c1, c2, c3, p10, p11, p12, p13, w2f[1][nt].x, w2f[1][nt].y);
            float* o0 = out + (b * TT + r0) * DM + cb;
            float* o1 = out + (b * TT + r0 + 8) * DM + cb;
            *reinterpret_cast<float2*>(o0) = make_float2(c0, c1);
            *reinterpret_cast<float2*>(o1) = make_float2(c2, c3);
        }
    }
}

extern "C" void kernel_launch(void* const* d_in, const int* in_sizes, int n_in,
                              void* d_out, int out_size)
{
    const float* x = (const float*)d_in[0];
    float* out = (float*)d_out;

    pack_kernel<<<1, 256>>>((const float*)d_in[1], (const float*)d_in[2],
                            (const float*)d_in[3], (const float*)d_in[4],
                            (const float*)d_in[5], (const float*)d_in[6],
                            (const float*)d_in[7], (const float*)d_in[8],
                            (const float*)d_in[9], (const float*)d_in[10],
                            (const float*)d_in[11]);
    void* src = nullptr;
    cudaGetSymbolAddress(&src, gPf);
    cudaMemcpyToSymbolAsync(cPf, src, NPARAM * sizeof(float), 0,
                            cudaMemcpyDeviceToDevice);

    int B = in_sizes[0] / (TT * DM);
    dim3 grid((B + 3) / 4);
    block_kernel<<<grid, 128>>>(x, out);
}

// round 10
// speedup vs baseline: 3.3122x; 1.1138x over previous
#include <cuda_runtime.h>
#include <cuda_fp16.h>
#include <math.h>

#define TT 64
#define DM 16
#define DFF 32
#define EPSF 1e-5f

// flat parameter bank offsets (floats)
#define OFF_WK  0
#define OFF_WQ  256
#define OFF_WV  512
#define OFF_W1  768
#define OFF_W2  1280
#define OFF_B1  1792
#define OFF_B2  1824
#define OFF_G1  1840
#define OFF_BE1 1856
#define OFF_G2  1872
#define OFF_BE2 1888
#define NPARAM  1904

__constant__ __align__(16) float cPf[NPARAM];
__device__   __align__(16) float gPf[NPARAM];

typedef unsigned long long u64;
typedef unsigned int u32;

// Precomputed fp16 B-fragments (m16n8k16 layout), per-lane tables
__device__ __align__(16) uint2 gFK[2][32];
__device__ __align__(16) uint2 gFQ[2][32];        // x0.25 folded
__device__ __align__(16) uint2 gFV[2][32];
__device__ __align__(16) uint2 gFW1[4][32];
__device__ __align__(16) uint2 gFW2[2][2][32];

// per-warp smem layout (bytes):
//  H    [64 rows][20 halves] @ 0     (2560)  h1 rows, then h2 rows
//  y    [64 rows][20 floats] @ 2560  (5120)
//  x    [64 rows][16 floats] @ 7680  (4096)  x rows, then (x'+b2) rows
#define HOFF 0
#define YOFF 2560
#define XOFF 7680
#define WARP_BYTES 11776

__device__ __forceinline__ u64 pk2(float lo, float hi) {
    u64 r; asm("mov.b64 %0,{%1,%2};" : "=l"(r) : "f"(lo), "f"(hi)); return r;
}
__device__ __forceinline__ float2 up2(u64 v) {
    float2 f; asm("mov.b64 {%0,%1},%2;" : "=f"(f.x), "=f"(f.y) : "l"(v)); return f;
}
__device__ __forceinline__ u64 f2fma(u64 a, u64 b, u64 c) {
    u64 d; asm("fma.rn.f32x2 %0,%1,%2,%3;" : "=l"(d) : "l"(a), "l"(b), "l"(c)); return d;
}
__device__ __forceinline__ u64 f2add(u64 a, u64 b) {
    u64 d; asm("add.rn.f32x2 %0,%1,%2;" : "=l"(d) : "l"(a), "l"(b)); return d;
}
__device__ __forceinline__ u64 ldc2(int off) {
    return *reinterpret_cast<const u64*>(&cPf[off]);
}
__device__ __forceinline__ u32 h2(float hi, float lo) {
    u32 r; asm("cvt.rn.f16x2.f32 %0, %1, %2;" : "=r"(r) : "f"(hi), "f"(lo)); return r;
}
// warp-collective 8x8 b16 transpose in mma fragment distribution
__device__ __forceinline__ u32 movm(u32 a) {
    u32 d; asm("movmatrix.sync.aligned.m8n8.trans.b16 %0, %1;" : "=r"(d) : "r"(a));
    return d;
}
__device__ __forceinline__ void mma16816(float& c0, float& c1, float& c2, float& c3,
                                         u32 a0, u32 a1, u32 a2, u32 a3,
                                         u32 b0, u32 b1)
{
    asm volatile("mma.sync.aligned.m16n8k16.row.col.f32.f16.f16.f32 "
                 "{%0,%1,%2,%3}, {%4,%5,%6,%7}, {%8,%9}, {%0,%1,%2,%3};"
                 : "+f"(c0), "+f"(c1), "+f"(c2), "+f"(c3)
                 : "r"(a0), "r"(a1), "r"(a2), "r"(a3), "r"(b0), "r"(b1));
}

__device__ __forceinline__ float gelu_f(float xv) {
    float t = xv * xv;
    float u = fmaf(t, -0.07135481627f, -1.59576912161f);
    float e = __expf(xv * u);
    return __fdividef(xv, 1.0f + e);
}

// ---- pack kernel: scalar params + fp16 B-fragment tables ----
__global__ void pack_kernel(const float* Wk, const float* Wq, const float* Wv,
                            const float* g1, const float* B1,
                            const float* g2, const float* B2,
                            const float* W1, const float* b1,
                            const float* W2, const float* b2)
{
    int i = threadIdx.x;
    if (i < 256) { gPf[OFF_WK + i] = Wk[i]; gPf[OFF_WQ + i] = Wq[i]; gPf[OFF_WV + i] = Wv[i]; }
    for (int j = i; j < 512; j += 256) { gPf[OFF_W1 + j] = W1[j]; gPf[OFF_W2 + j] = W2[j]; }
    if (i < DFF) gPf[OFF_B1 + i] = b1[i];
    if (i < DM) {
        gPf[OFF_B2 + i]  = b2[i];
        gPf[OFF_G1 + i]  = g1[i];  gPf[OFF_BE1 + i] = B1[i];
        gPf[OFF_G2 + i]  = g2[i];  gPf[OFF_BE2 + i] = B2[i];
    }

    int lane = i & 31;
    int qd = lane & 3, g = lane >> 2;
    if (i < 192) {
        int wsel = i >> 6, nt = (i >> 5) & 1;
        const float* W = (wsel == 0) ? Wk : (wsel == 1) ? Wq : Wv;
        float sc = (wsel == 1) ? 0.25f : 1.0f;
        int j = nt * 8 + g;
        uint2 fr;
        fr.x = h2(sc * W[(2*qd+1)*DM + j], sc * W[(2*qd  )*DM + j]);
        fr.y = h2(sc * W[(2*qd+9)*DM + j], sc * W[(2*qd+8)*DM + j]);
        if (wsel == 0) gFK[nt][lane] = fr;
        else if (wsel == 1) gFQ[nt][lane] = fr;
        else gFV[nt][lane] = fr;
    }
    if (i < 128) {
        int nt = i >> 5;
        int j = nt * 8 + g;
        uint2 fr;
        fr.x = h2(W1[(2*qd+1)*DFF + j], W1[(2*qd  )*DFF + j]);
        fr.y = h2(W1[(2*qd+9)*DFF + j], W1[(2*qd+8)*DFF + j]);
        gFW1[nt][lane] = fr;
    }
    if (i < 128) {
        int ks = i >> 6, nt = (i >> 5) & 1;
        int j = nt * 8 + g;
        int kb = ks * 16;
        uint2 fr;
        fr.x = h2(W2[(kb+2*qd+1)*DM + j], W2[(kb+2*qd  )*DM + j]);
        fr.y = h2(W2[(kb+2*qd+9)*DM + j], W2[(kb+2*qd+8)*DM + j]);
        gFW2[ks][nt][lane] = fr;
    }
}

template <int GOFF, int BOFF>
__device__ __forceinline__ void ln16c(const u64* xp, float* hs)
{
    u64 acc = f2add(f2add(f2add(xp[0], xp[1]), f2add(xp[2], xp[3])),
                    f2add(f2add(xp[4], xp[5]), f2add(xp[6], xp[7])));
    float2 s2 = up2(acc);
    float mu = (s2.x + s2.y) * (1.0f / DM);
    u64 nmu = pk2(-mu, -mu);
    u64 v0 = 0ull, v1 = 0ull;
    #pragma unroll
    for (int i = 0; i < 8; i += 2) {
        u64 d0 = f2add(xp[i], nmu);     v0 = f2fma(d0, d0, v0);
        u64 d1 = f2add(xp[i + 1], nmu); v1 = f2fma(d1, d1, v1);
    }
    s2 = up2(f2add(v0, v1));
    float rstd = rsqrtf((s2.x + s2.y) * (1.0f / DM) + EPSF);
    #pragma unroll
    for (int c = 0; c < DM; c++) {
        float2 xv = up2(xp[c >> 1]);
        float xc = (c & 1) ? xv.y : xv.x;
        hs[c] = (xc - mu) * rstd * cPf[GOFF + c] + cPf[BOFF + c];
    }
}

__device__ __forceinline__ void st_row_h16(char* hp, const float* hs)
{
    #pragma unroll
    for (int i = 0; i < 4; i++) {
        u32 p0 = h2(hs[4 * i + 1], hs[4 * i]);
        u32 p1 = h2(hs[4 * i + 3], hs[4 * i + 2]);
        *reinterpret_cast<uint2*>(hp + i * 8) = make_uint2(p0, p1);
    }
}

__global__ __launch_bounds__(128, 4)
void block_kernel(const float* __restrict__ x, float* __restrict__ out)
{
    __shared__ __align__(16) char smem[4 * WARP_BYTES];

    const int tid = threadIdx.x;
    const int w   = tid >> 5;
    const int t   = tid & 31;
    const int g   = t >> 2;
    const int qd  = t & 3;
    char* Sb = smem + w * WARP_BYTES;
    const long long b = (long long)blockIdx.x * 4 + w;

    // ---- phase 1: load x, LN1, stage h1 fp16 rows + x rows ----
    {
        u64 xA[8], xB[8];
        const float* xa = x + (b * TT + t) * DM;
        #pragma unroll
        for (int i = 0; i < 4; i++) {
            ulonglong2 v = *reinterpret_cast<const ulonglong2*>(xa + 4 * i);
            xA[2 * i] = v.x; xA[2 * i + 1] = v.y;
            *reinterpret_cast<ulonglong2*>(Sb + XOFF + t * 64 + i * 16) = v;
            ulonglong2 u = *reinterpret_cast<const ulonglong2*>(xa + 32 * DM + 4 * i);
            xB[2 * i] = u.x; xB[2 * i + 1] = u.y;
            *reinterpret_cast<ulonglong2*>(Sb + XOFF + (t + 32) * 64 + i * 16) = u;
        }
        float hA[DM], hB[DM];
        ln16c<OFF_G1, OFF_BE1>(xA, hA);
        ln16c<OFF_G1, OFF_BE1>(xB, hB);
        st_row_h16(Sb + HOFF + t * 40, hA);
        st_row_h16(Sb + HOFF + (t + 32) * 40, hB);
    }
    __syncwarp();

    // ---- phase 2: QKV projections via MMA; fragments stay in registers ----
    u32 qa[4][4], kb0[8], kb1[8], vb0[4][2], vb1[4][2];
    {
        uint2 fq0 = gFQ[0][t], fq1 = gFQ[1][t];
        uint2 fk0 = gFK[0][t], fk1 = gFK[1][t];
        uint2 fv0 = gFV[0][t], fv1 = gFV[1][t];
        #pragma unroll
        for (int m = 0; m < 4; m++) {
            const char* hp0 = Sb + HOFF + (m * 16 + g) * 40 + qd * 4;
            const char* hp1 = Sb + HOFF + (m * 16 + g + 8) * 40 + qd * 4;
            u32 a0 = *reinterpret_cast<const u32*>(hp0);
            u32 a1 = *reinterpret_cast<const u32*>(hp1);
            u32 a2 = *reinterpret_cast<const u32*>(hp0 + 16);
            u32 a3 = *reinterpret_cast<const u32*>(hp1 + 16);
            // Q: C-frag distribution == A-frag distribution (direct repack)
            {
                float c0=0,c1=0,c2=0,c3=0, d0=0,d1=0,d2=0,d3=0;
                mma16816(c0,c1,c2,c3, a0,a1,a2,a3, fq0.x,fq0.y);
                mma16816(d0,d1,d2,d3, a0,a1,a2,a3, fq1.x,fq1.y);
                qa[m][0] = h2(c1, c0);
                qa[m][1] = h2(c3, c2);
                qa[m][2] = h2(d1, d0);
                qa[m][3] = h2(d3, d2);
            }
            // K: C-frag distribution == B-frag distribution (direct repack)
            {
                float c0=0,c1=0,c2=0,c3=0, d0=0,d1=0,d2=0,d3=0;
                mma16816(c0,c1,c2,c3, a0,a1,a2,a3, fk0.x,fk0.y);
                mma16816(d0,d1,d2,d3, a0,a1,a2,a3, fk1.x,fk1.y);
                kb0[2*m]     = h2(c1, c0);
                kb0[2*m + 1] = h2(c3, c2);
                kb1[2*m]     = h2(d1, d0);
                kb1[2*m + 1] = h2(d3, d2);
            }
            // V: need transpose -> movmatrix (8x8 b16 in fragment distribution)
            {
                float c0=0,c1=0,c2=0,c3=0, d0=0,d1=0,d2=0,d3=0;
                mma16816(c0,c1,c2,c3, a0,a1,a2,a3, fv0.x,fv0.y);
                mma16816(d0,d1,d2,d3, a0,a1,a2,a3, fv1.x,fv1.y);
                vb0[m][0] = movm(h2(c1, c0));
                vb1[m][0] = movm(h2(c3, c2));
                vb0[m][1] = movm(h2(d1, d0));
                vb1[m][1] = movm(h2(d3, d2));
            }
        }
    }

    // ---- phase 3: attention via MMA (all operands register-resident) ----
    #pragma unroll
    for (int m = 0; m < 4; m++) {
        const int r0 = m * 16 + g, r1 = r0 + 8;
        float e[8][4];
        float l0 = 0.f, l1 = 0.f;
        #pragma unroll
        for (int j = 0; j < 8; j++) {
            if (j > 2 * m + 1) continue;
            float c0 = 0.f, c1 = 0.f, c2 = 0.f, c3 = 0.f;
            mma16816(c0, c1, c2, c3, qa[m][0], qa[m][1], qa[m][2], qa[m][3],
                     kb0[j], kb1[j]);
            int col = j * 8 + 2 * qd;
            e[j][0] = (col     <= r0) ? __expf(c0) : 0.f;
            e[j][1] = (col + 1 <= r0) ? __expf(c1) : 0.f;
            e[j][2] = (col     <= r1) ? __expf(c2) : 0.f;
            e[j][3] = (col + 1 <= r1) ? __expf(c3) : 0.f;
            l0 += e[j][0] + e[j][1];
            l1 += e[j][2] + e[j][3];
        }
        l0 += __shfl_xor_sync(0xffffffff, l0, 1);
        l0 += __shfl_xor_sync(0xffffffff, l0, 2);
        l1 += __shfl_xor_sync(0xffffffff, l1, 1);
        l1 += __shfl_xor_sync(0xffffffff, l1, 2);
        float inv0 = __fdividef(1.0f, l0), inv1 = __fdividef(1.0f, l1);

        u32 pa[4][4];
        #pragma unroll
        for (int s = 0; s < 4; s++) {
            if (s > m) continue;
            pa[s][0] = h2(e[2 * s][1],     e[2 * s][0]);
            pa[s][1] = h2(e[2 * s][3],     e[2 * s][2]);
            pa[s][2] = h2(e[2 * s + 1][1], e[2 * s + 1][0]);
            pa[s][3] = h2(e[2 * s + 1][3], e[2 * s + 1][2]);
        }
        #pragma unroll
        for (int nt = 0; nt < 2; nt++) {
            float y0 = 0.f, y1 = 0.f, y2 = 0.f, y3 = 0.f;
            #pragma unroll
            for (int s = 0; s < 4; s++) {
                if (s > m) continue;
                mma16816(y0, y1, y2, y3,
                         pa[s][0], pa[s][1], pa[s][2], pa[s][3],
                         vb0[s][nt], vb1[s][nt]);
            }
            float* yp0 = reinterpret_cast<float*>(Sb + YOFF + r0 * 80 + (nt * 8 + 2 * qd) * 4);
            float* yp1 = reinterpret_cast<float*>(Sb + YOFF + r1 * 80 + (nt * 8 + 2 * qd) * 4);
            *reinterpret_cast<float2*>(yp0) = make_float2(y0 * inv0, y1 * inv0);
            *reinterpret_cast<float2*>(yp1) = make_float2(y2 * inv1, y3 * inv1);
        }
    }
    __syncwarp();

    // ---- phase 4: residual + LN2 (scalar), stage h2 fp16 + (x'+b2) rows ----
    {
        u64 xA[8], xB[8];
        const char* xs  = Sb + XOFF + t * 64;
        const char* xs2 = Sb + XOFF + (t + 32) * 64;
        const char* ys  = Sb + YOFF + t * 80;
        const char* ys2 = Sb + YOFF + (t + 32) * 80;
        #pragma unroll
        for (int i = 0; i < 4; i++) {
            ulonglong2 vx = *reinterpret_cast<const ulonglong2*>(xs + i * 16);
            ulonglong2 vy = *reinterpret_cast<const ulonglong2*>(ys + i * 16);
            xA[2 * i]     = f2add(vx.x, vy.x);
            xA[2 * i + 1] = f2add(vx.y, vy.y);
            ulonglong2 ux = *reinterpret_cast<const ulonglong2*>(xs2 + i * 16);
            ulonglong2 uy = *reinterpret_cast<const ulonglong2*>(ys2 + i * 16);
            xB[2 * i]     = f2add(ux.x, uy.x);
            xB[2 * i + 1] = f2add(ux.y, uy.y);
        }
        float hA[DM], hB[DM];
        ln16c<OFF_G2, OFF_BE2>(xA, hA);
        ln16c<OFF_G2, OFF_BE2>(xB, hB);
        st_row_h16(Sb + HOFF + t * 40, hA);
        st_row_h16(Sb + HOFF + (t + 32) * 40, hB);
        #pragma unroll
        for (int i = 0; i < 8; i++) {
            u64 bp = ldc2(OFF_B2 + 2 * i);
            xA[i] = f2add(xA[i], bp);
            xB[i] = f2add(xB[i], bp);
        }
        #pragma unroll
        for (int i = 0; i < 4; i++) {
            *reinterpret_cast<ulonglong2*>(Sb + XOFF + t * 64 + i * 16) =
                make_ulonglong2(xA[2 * i], xA[2 * i + 1]);
            *reinterpret_cast<ulonglong2*>(Sb + XOFF + (t + 32) * 64 + i * 16) =
                make_ulonglong2(xB[2 * i], xB[2 * i + 1]);
        }
    }
    __syncwarp();

    // ---- phase 5: FFN via MMA ----
    uint2 w1f[4] = { gFW1[0][t], gFW1[1][t], gFW1[2][t], gFW1[3][t] };
    uint2 w2f[2][2] = { { gFW2[0][0][t], gFW2[0][1][t] },
                        { gFW2[1][0][t], gFW2[1][1][t] } };
    float2 b1v[4];
    #pragma unroll
    for (int nt = 0; nt < 4; nt++)
        b1v[nt] = make_float2(cPf[OFF_B1 + nt * 8 + 2 * qd],
                              cPf[OFF_B1 + nt * 8 + 2 * qd + 1]);

    #pragma unroll
    for (int m = 0; m < 4; m++) {
        const int r0 = m * 16 + g;
        const char* hp0 = Sb + HOFF + r0 * 40 + qd * 4;
        const char* hp1 = Sb + HOFF + (r0 + 8) * 40 + qd * 4;
        u32 a0 = *reinterpret_cast<const u32*>(hp0);
        u32 a1 = *reinterpret_cast<const u32*>(hp1);
        u32 a2 = *reinterpret_cast<const u32*>(hp0 + 16);
        u32 a3 = *reinterpret_cast<const u32*>(hp1 + 16);

        float gl[4][4];
        #pragma unroll
        for (int nt = 0; nt < 4; nt++) {
            float c0 = b1v[nt].x, c1 = b1v[nt].y, c2 = b1v[nt].x, c3 = b1v[nt].y;
            mma16816(c0, c1, c2, c3, a0, a1, a2, a3, w1f[nt].x, w1f[nt].y);
            gl[nt][0] = gelu_f(c0); gl[nt][1] = gelu_f(c1);
            gl[nt][2] = gelu_f(c2); gl[nt][3] = gelu_f(c3);
        }
        u32 p00 = h2(gl[0][1], gl[0][0]), p01 = h2(gl[0][3], gl[0][2]);
        u32 p02 = h2(gl[1][1], gl[1][0]), p03 = h2(gl[1][3], gl[1][2]);
        u32 p10 = h2(gl[2][1], gl[2][0]), p11 = h2(gl[2][3], gl[2][2]);
        u32 p12 = h2(gl[3][1], gl[3][0]), p13 = h2(gl[3][3], gl[3][2]);

        #pragma unroll
        for (int nt = 0; nt < 2; nt++) {
            const int cb = nt * 8 + 2 * qd;
            float2 d0 = *reinterpret_cast<const float2*>(Sb + XOFF + r0 * 64 + cb * 4);
            float2 d1 = *reinterpret_cast<const float2*>(Sb + XOFF + (r0 + 8) * 64 + cb * 4);
            float c0 = d0.x, c1 = d0.y, c2 = d1.x, c3 = d1.y;
            mma16816(c0, c1, c2, c3, p00, p01, p02, p03, w2f[0][nt].x, w2f[0][nt].y);
            mma16816(c0, c1, c2, c3, p10, p11, p12, p13, w2f[1][nt].x, w2f[1][nt].y);
            float* o0 = out + (b * TT + r0) * DM + cb;
            float* o1 = out + (b * TT + r0 + 8) * DM + cb;
            *reinterpret_cast<float2*>(o0) = make_float2(c0, c1);
            *reinterpret_cast<float2*>(o1) = make_float2(c2, c3);
        }
    }
}

extern "C" void kernel_launch(void* const* d_in, const int* in_sizes, int n_in,
                              void* d_out, int out_size)
{
    const float* x = (const float*)d_in[0];
    float* out = (float*)d_out;

    pack_kernel<<<1, 256>>>((const float*)d_in[1], (const float*)d_in[2],
                            (const float*)d_in[3], (const float*)d_in[4],
                            (const float*)d_in[5], (const float*)d_in[6],
                            (const float*)d_in[7], (const float*)d_in[8],
                            (const float*)d_in[9], (const float*)d_in[10],
                            (const float*)d_in[11]);
    void* src = nullptr;
    cudaGetSymbolAddress(&src, gPf);
    cudaMemcpyToSymbolAsync(cPf, src, NPARAM * sizeof(float), 0,
                            cudaMemcpyDeviceToDevice);

    int B = in_sizes[0] / (TT * DM);
    dim3 grid((B + 3) / 4);
    block_kernel<<<grid, 128>>>(x, out);
}

// round 12
// speedup vs baseline: 3.9943x; 1.2059x over previous
#include <cuda_runtime.h>
#include <cuda_fp16.h>
#include <math.h>

#define TT 64
#define DM 16
#define DFF 32
#define EPSF 1e-5f

// flat parameter bank offsets (floats)
#define OFF_WK  0
#define OFF_WQ  256
#define OFF_WV  512
#define OFF_W1  768
#define OFF_W2  1280
#define OFF_B1  1792
#define OFF_B2  1824
#define OFF_G1  1840
#define OFF_BE1 1856
#define OFF_G2  1872
#define OFF_BE2 1888
#define NPARAM  1904

__constant__ __align__(16) float cPf[NPARAM];
__device__   __align__(16) float gPf[NPARAM];

typedef unsigned long long u64;
typedef unsigned int u32;

// Precomputed fp16 B-fragments (m16n8k16 layout), per-lane tables
__device__ __align__(16) uint2 gFK[2][32];
__device__ __align__(16) uint2 gFQ[2][32];        // x0.25 folded
__device__ __align__(16) uint2 gFV[2][32];
__device__ __align__(16) uint2 gFW1[4][32];
__device__ __align__(16) uint2 gFW2[2][2][32];

__device__ __forceinline__ float2 up2(u64 v) {
    float2 f; asm("mov.b64 {%0,%1},%2;" : "=f"(f.x), "=f"(f.y) : "l"(v)); return f;
}
__device__ __forceinline__ u64 ldc2(int off) {
    return *reinterpret_cast<const u64*>(&cPf[off]);
}
__device__ __forceinline__ u32 h2(float hi, float lo) {
    u32 r; asm("cvt.rn.f16x2.f32 %0, %1, %2;" : "=r"(r) : "f"(hi), "f"(lo)); return r;
}
__device__ __forceinline__ u32 movm(u32 a) {
    u32 d; asm("movmatrix.sync.aligned.m8n8.trans.b16 %0, %1;" : "=r"(d) : "r"(a));
    return d;
}
__device__ __forceinline__ void mma16816(float& c0, float& c1, float& c2, float& c3,
                                         u32 a0, u32 a1, u32 a2, u32 a3,
                                         u32 b0, u32 b1)
{
    asm volatile("mma.sync.aligned.m16n8k16.row.col.f32.f16.f16.f32 "
                 "{%0,%1,%2,%3}, {%4,%5,%6,%7}, {%8,%9}, {%0,%1,%2,%3};"
                 : "+f"(c0), "+f"(c1), "+f"(c2), "+f"(c3)
                 : "r"(a0), "r"(a1), "r"(a2), "r"(a3), "r"(b0), "r"(b1));
}

__device__ __forceinline__ float gelu_f(float xv) {
    float t = xv * xv;
    float u = fmaf(t, -0.07135481627f, -1.59576912161f);
    float e = __expf(xv * u);
    return __fdividef(xv, 1.0f + e);
}
__device__ __forceinline__ float qsum(float v) {   // quad (qd) reduction
    v += __shfl_xor_sync(0xffffffff, v, 1);
    v += __shfl_xor_sync(0xffffffff, v, 2);
    return v;
}

// ---- pack kernel: scalar params + fp16 B-fragment tables ----
__global__ void pack_kernel(const float* Wk, const float* Wq, const float* Wv,
                            const float* g1, const float* B1,
                            const float* g2, const float* B2,
                            const float* W1, const float* b1,
                            const float* W2, const float* b2)
{
    int i = threadIdx.x;
    if (i < 256) { gPf[OFF_WK + i] = Wk[i]; gPf[OFF_WQ + i] = Wq[i]; gPf[OFF_WV + i] = Wv[i]; }
    for (int j = i; j < 512; j += 256) { gPf[OFF_W1 + j] = W1[j]; gPf[OFF_W2 + j] = W2[j]; }
    if (i < DFF) gPf[OFF_B1 + i] = b1[i];
    if (i < DM) {
        gPf[OFF_B2 + i]  = b2[i];
        gPf[OFF_G1 + i]  = g1[i];  gPf[OFF_BE1 + i] = B1[i];
        gPf[OFF_G2 + i]  = g2[i];  gPf[OFF_BE2 + i] = B2[i];
    }

    int lane = i & 31;
    int qd = lane & 3, g = lane >> 2;
    if (i < 192) {
        int wsel = i >> 6, nt = (i >> 5) & 1;
        const float* W = (wsel == 0) ? Wk : (wsel == 1) ? Wq : Wv;
        float sc = (wsel == 1) ? 0.25f : 1.0f;
        int j = nt * 8 + g;
        uint2 fr;
        fr.x = h2(sc * W[(2*qd+1)*DM + j], sc * W[(2*qd  )*DM + j]);
        fr.y = h2(sc * W[(2*qd+9)*DM + j], sc * W[(2*qd+8)*DM + j]);
        if (wsel == 0) gFK[nt][lane] = fr;
        else if (wsel == 1) gFQ[nt][lane] = fr;
        else gFV[nt][lane] = fr;
    }
    if (i < 128) {
        int nt = i >> 5;
        int j = nt * 8 + g;
        uint2 fr;
        fr.x = h2(W1[(2*qd+1)*DFF + j], W1[(2*qd  )*DFF + j]);
        fr.y = h2(W1[(2*qd+9)*DFF + j], W1[(2*qd+8)*DFF + j]);
        gFW1[nt][lane] = fr;
    }
    if (i < 128) {
        int ks = i >> 6, nt = (i >> 5) & 1;
        int j = nt * 8 + g;
        int kb = ks * 16;
        uint2 fr;
        fr.x = h2(W2[(kb+2*qd+1)*DM + j], W2[(kb+2*qd  )*DM + j]);
        fr.y = h2(W2[(kb+2*qd+9)*DM + j], W2[(kb+2*qd+8)*DM + j]);
        gFW2[ks][nt][lane] = fr;
    }
}

__global__ __launch_bounds__(128, 4)
void block_kernel(const float* __restrict__ x, float* __restrict__ out)
{
    const int tid = threadIdx.x;
    const int w   = tid >> 5;
    const int t   = tid & 31;
    const int g   = t >> 2;
    const int qd  = t & 3;
    const long long b = (long long)blockIdx.x * 4 + w;
    const float* xb = x + b * TT * DM;
    float* ob = out + b * TT * DM;

    // per-lane LN1 params (cols 2qd,2qd+1 and 8+2qd,8+2qd+1)
    const int c2 = 2 * qd;
    float2 g1a = up2(ldc2(OFF_G1 + c2)),      g1b = up2(ldc2(OFF_G1 + 8 + c2));
    float2 n1a = up2(ldc2(OFF_BE1 + c2)),     n1b = up2(ldc2(OFF_BE1 + 8 + c2));

    // ---- phase 1+2: load x in fragment layout, LN1 in-frag, QKV proj ----
    u32 qa[4][4], kb0[8], kb1[8], vb0[4][2], vb1[4][2];
    {
        uint2 fq0 = gFQ[0][t], fq1 = gFQ[1][t];
        uint2 fk0 = gFK[0][t], fk1 = gFK[1][t];
        uint2 fv0 = gFV[0][t], fv1 = gFV[1][t];
        #pragma unroll
        for (int m = 0; m < 4; m++) {
            const float* p0 = xb + (m * 16 + g) * DM + c2;
            float2 x00 = *reinterpret_cast<const float2*>(p0);            // r0, nt0
            float2 x01 = *reinterpret_cast<const float2*>(p0 + 8);        // r0, nt1
            float2 x10 = *reinterpret_cast<const float2*>(p0 + 8 * DM);   // r1, nt0
            float2 x11 = *reinterpret_cast<const float2*>(p0 + 8 * DM + 8);

            // LN1 via quad reductions
            float mu0 = qsum(x00.x + x00.y + x01.x + x01.y) * (1.0f / DM);
            float mu1 = qsum(x10.x + x10.y + x11.x + x11.y) * (1.0f / DM);
            float d, v0 = 0.f, v1 = 0.f;
            d = x00.x - mu0; v0 += d * d;  d = x00.y - mu0; v0 += d * d;
            d = x01.x - mu0; v0 += d * d;  d = x01.y - mu0; v0 += d * d;
            d = x10.x - mu1; v1 += d * d;  d = x10.y - mu1; v1 += d * d;
            d = x11.x - mu1; v1 += d * d;  d = x11.y - mu1; v1 += d * d;
            float r0s = rsqrtf(qsum(v0) * (1.0f / DM) + EPSF);
            float r1s = rsqrtf(qsum(v1) * (1.0f / DM) + EPSF);

            // h as A-fragment (C->A identity)
            u32 a0 = h2((x00.y - mu0) * r0s * g1a.y + n1a.y,
                        (x00.x - mu0) * r0s * g1a.x + n1a.x);
            u32 a1 = h2((x10.y - mu1) * r1s * g1a.y + n1a.y,
                        (x10.x - mu1) * r1s * g1a.x + n1a.x);
            u32 a2 = h2((x01.y - mu0) * r0s * g1b.y + n1b.y,
                        (x01.x - mu0) * r0s * g1b.x + n1b.x);
            u32 a3 = h2((x11.y - mu1) * r1s * g1b.y + n1b.y,
                        (x11.x - mu1) * r1s * g1b.x + n1b.x);

            // Q -> A-frags
            {
                float c0=0,c1=0,cc2=0,c3=0, d0=0,d1=0,d2=0,d3=0;
                mma16816(c0,c1,cc2,c3, a0,a1,a2,a3, fq0.x,fq0.y);
                mma16816(d0,d1,d2,d3, a0,a1,a2,a3, fq1.x,fq1.y);
                qa[m][0] = h2(c1, c0);
                qa[m][1] = h2(c3, cc2);
                qa[m][2] = h2(d1, d0);
                qa[m][3] = h2(d3, d2);
            }
            // K -> B-frags
            {
                float c0=0,c1=0,cc2=0,c3=0, d0=0,d1=0,d2=0,d3=0;
                mma16816(c0,c1,cc2,c3, a0,a1,a2,a3, fk0.x,fk0.y);
                mma16816(d0,d1,d2,d3, a0,a1,a2,a3, fk1.x,fk1.y);
                kb0[2*m]     = h2(c1, c0);
                kb0[2*m + 1] = h2(c3, cc2);
                kb1[2*m]     = h2(d1, d0);
                kb1[2*m + 1] = h2(d3, d2);
            }
            // V -> transposed B-frags via movmatrix
            {
                float c0=0,c1=0,cc2=0,c3=0, d0=0,d1=0,d2=0,d3=0;
                mma16816(c0,c1,cc2,c3, a0,a1,a2,a3, fv0.x,fv0.y);
                mma16816(d0,d1,d2,d3, a0,a1,a2,a3, fv1.x,fv1.y);
                vb0[m][0] = movm(h2(c1, c0));
                vb1[m][0] = movm(h2(c3, cc2));
                vb0[m][1] = movm(h2(d1, d0));
                vb1[m][1] = movm(h2(d3, d2));
            }
        }
    }

    // per-lane LN2 / bias params + FFN weight frags
    float2 g2a = up2(ldc2(OFF_G2 + c2)),  g2b = up2(ldc2(OFF_G2 + 8 + c2));
    float2 n2a = up2(ldc2(OFF_BE2 + c2)), n2b = up2(ldc2(OFF_BE2 + 8 + c2));
    float2 b2a = up2(ldc2(OFF_B2 + c2)),  b2b = up2(ldc2(OFF_B2 + 8 + c2));
    float2 b1v[4];
    #pragma unroll
    for (int nt = 0; nt < 4; nt++)
        b1v[nt] = up2(ldc2(OFF_B1 + nt * 8 + c2));
    uint2 w1f[4] = { gFW1[0][t], gFW1[1][t], gFW1[2][t], gFW1[3][t] };
    uint2 w2f[2][2] = { { gFW2[0][0][t], gFW2[0][1][t] },
                        { gFW2[1][0][t], gFW2[1][1][t] } };

    // ---- phase 3-5 fused per m-tile: attention, residual, LN2, FFN, store ----
    #pragma unroll
    for (int m = 0; m < 4; m++) {
        const int r0 = m * 16 + g, r1 = r0 + 8;
        float e[8][4];
        float l0 = 0.f, l1 = 0.f;
        #pragma unroll
        for (int j = 0; j < 8; j++) {
            if (j > 2 * m + 1) continue;
            float c0 = 0.f, c1 = 0.f, cc2 = 0.f, c3 = 0.f;
            mma16816(c0, c1, cc2, c3, qa[m][0], qa[m][1], qa[m][2], qa[m][3],
                     kb0[j], kb1[j]);
            int col = j * 8 + c2;
            e[j][0] = (col     <= r0) ? __expf(c0) : 0.f;
            e[j][1] = (col + 1 <= r0) ? __expf(c1) : 0.f;
            e[j][2] = (col     <= r1) ? __expf(cc2) : 0.f;
            e[j][3] = (col + 1 <= r1) ? __expf(c3) : 0.f;
            l0 += e[j][0] + e[j][1];
            l1 += e[j][2] + e[j][3];
        }
        l0 = qsum(l0); l1 = qsum(l1);
        float inv0 = __fdividef(1.0f, l0), inv1 = __fdividef(1.0f, l1);

        u32 pa[4][4];
        #pragma unroll
        for (int s = 0; s < 4; s++) {
            if (s > m) continue;
            pa[s][0] = h2(e[2 * s][1],     e[2 * s][0]);
            pa[s][1] = h2(e[2 * s][3],     e[2 * s][2]);
            pa[s][2] = h2(e[2 * s + 1][1], e[2 * s + 1][0]);
            pa[s][3] = h2(e[2 * s + 1][3], e[2 * s + 1][2]);
        }

        // y via MMA, fuse residual with x re-read from global
        float xn[2][4];
        #pragma unroll
        for (int nt = 0; nt < 2; nt++) {
            float y0 = 0.f, y1 = 0.f, y2 = 0.f, y3 = 0.f;
            #pragma unroll
            for (int s = 0; s < 4; s++) {
                if (s > m) continue;
                mma16816(y0, y1, y2, y3,
                         pa[s][0], pa[s][1], pa[s][2], pa[s][3],
                         vb0[s][nt], vb1[s][nt]);
            }
            const float* p0 = xb + r0 * DM + nt * 8 + c2;
            float2 xl0 = *reinterpret_cast<const float2*>(p0);
            float2 xl1 = *reinterpret_cast<const float2*>(p0 + 8 * DM);
            xn[nt][0] = fmaf(y0, inv0, xl0.x);
            xn[nt][1] = fmaf(y1, inv0, xl0.y);
            xn[nt][2] = fmaf(y2, inv1, xl1.x);
            xn[nt][3] = fmaf(y3, inv1, xl1.y);
        }

        // LN2 in-frag
        float mu0 = qsum(xn[0][0] + xn[0][1] + xn[1][0] + xn[1][1]) * (1.0f / DM);
        float mu1 = qsum(xn[0][2] + xn[0][3] + xn[1][2] + xn[1][3]) * (1.0f / DM);
        float d, v0 = 0.f, v1 = 0.f;
        d = xn[0][0] - mu0; v0 += d * d;  d = xn[0][1] - mu0; v0 += d * d;
        d = xn[1][0] - mu0; v0 += d * d;  d = xn[1][1] - mu0; v0 += d * d;
        d = xn[0][2] - mu1; v1 += d * d;  d = xn[0][3] - mu1; v1 += d * d;
        d = xn[1][2] - mu1; v1 += d * d;  d = xn[1][3] - mu1; v1 += d * d;
        float r0s = rsqrtf(qsum(v0) * (1.0f / DM) + EPSF);
        float r1s = rsqrtf(qsum(v1) * (1.0f / DM) + EPSF);

        u32 a0 = h2((xn[0][1] - mu0) * r0s * g2a.y + n2a.y,
                    (xn[0][0] - mu0) * r0s * g2a.x + n2a.x);
        u32 a1 = h2((xn[0][3] - mu1) * r1s * g2a.y + n2a.y,
                    (xn[0][2] - mu1) * r1s * g2a.x + n2a.x);
        u32 a2 = h2((xn[1][1] - mu0) * r0s * g2b.y + n2b.y,
                    (xn[1][0] - mu0) * r0s * g2b.x + n2b.x);
        u32 a3 = h2((xn[1][3] - mu1) * r1s * g2b.y + n2b.y,
                    (xn[1][2] - mu1) * r1s * g2b.x + n2b.x);

        // FFN1 -> GELU -> FFN2 A-frags
        float gl[4][4];
        #pragma unroll
        for (int nt = 0; nt < 4; nt++) {
            float c0 = b1v[nt].x, c1 = b1v[nt].y, cc2 = b1v[nt].x, c3 = b1v[nt].y;
            mma16816(c0, c1, cc2, c3, a0, a1, a2, a3, w1f[nt].x, w1f[nt].y);
            gl[nt][0] = gelu_f(c0); gl[nt][1] = gelu_f(c1);
            gl[nt][2] = gelu_f(cc2); gl[nt][3] = gelu_f(c3);
        }
        u32 p00 = h2(gl[0][1], gl[0][0]), p01 = h2(gl[0][3], gl[0][2]);
        u32 p02 = h2(gl[1][1], gl[1][0]), p03 = h2(gl[1][3], gl[1][2]);
        u32 p10 = h2(gl[2][1], gl[2][0]), p11 = h2(gl[2][3], gl[2][2]);
        u32 p12 = h2(gl[3][1], gl[3][0]), p13 = h2(gl[3][3], gl[3][2]);

        // FFN2 + residual (x'+b2 as accumulator init), store straight out
        #pragma unroll
        for (int nt = 0; nt < 2; nt++) {
            float2 bb = nt ? b2b : b2a;
            float c0 = xn[nt][0] + bb.x, c1 = xn[nt][1] + bb.y;
            float cc2 = xn[nt][2] + bb.x, c3 = xn[nt][3] + bb.y;
            mma16816(c0, c1, cc2, c3, p00, p01, p02, p03, w2f[0][nt].x, w2f[0][nt].y);
            mma16816(c0, c1, cc2, c3, p10, p11, p12, p13, w2f[1][nt].x, w2f[1][nt].y);
            float* o0 = ob + r0 * DM + nt * 8 + c2;
            *reinterpret_cast<float2*>(o0)          = make_float2(c0, c1);
            *reinterpret_cast<float2*>(o0 + 8 * DM) = make_float2(cc2, c3);
        }
    }
}

extern "C" void kernel_launch(void* const* d_in, const int* in_sizes, int n_in,
                              void* d_out, int out_size)
{
    const float* x = (const float*)d_in[0];
    float* out = (float*)d_out;

    pack_kernel<<<1, 256>>>((const float*)d_in[1], (const float*)d_in[2],
                            (const float*)d_in[3], (const float*)d_in[4],
                            (const float*)d_in[5], (const float*)d_in[6],
                            (const float*)d_in[7], (const float*)d_in[8],
                            (const float*)d_in[9], (const float*)d_in[10],
                            (const float*)d_in[11]);
    void* src = nullptr;
    cudaGetSymbolAddress(&src, gPf);
    cudaMemcpyToSymbolAsync(cPf, src, NPARAM * sizeof(float), 0,
                            cudaMemcpyDeviceToDevice);

    int B = in_sizes[0] / (TT * DM);
    dim3 grid((B + 3) / 4);
    block_kernel<<<grid, 128>>>(x, out);
}